// round 10
// baseline (speedup 1.0000x reference)
#include <cuda_runtime.h>
#include <cuda_fp16.h>
#include <math.h>
#include <stdint.h>

#define D_MODEL 1024
#define NHEADS  16
#define HDIM    64
#define BATCH   4
#define SEQ     2048
#define MROWS   (BATCH*SEQ)   // 8192

// Scratch (device globals — no allocations allowed). Halves stored as uint16_t.
__device__ uint16_t g_Q[(size_t)MROWS * D_MODEL];   // [B,H,S,hd] half
__device__ uint16_t g_K[(size_t)MROWS * D_MODEL];   // [B,H,S,hd] half
__device__ uint16_t g_V[(size_t)MROWS * D_MODEL];   // [B,H,hd,S] half (pre-transposed!)
__device__ uint16_t g_C[(size_t)MROWS * D_MODEL];   // [B,S,D]    half
// half TRANSPOSED weights: Wt[n][k] = half(W[k][n])
__device__ uint16_t g_Wq[(size_t)D_MODEL * D_MODEL];
__device__ uint16_t g_Wk[(size_t)D_MODEL * D_MODEL];
__device__ uint16_t g_Wv[(size_t)D_MODEL * D_MODEL];
__device__ uint16_t g_Wo[(size_t)D_MODEL * D_MODEL];

__device__ __forceinline__ uint32_t f2h2(float a, float b) {
    __half2 h = __floats2half2_rn(a, b);
    return *reinterpret_cast<uint32_t*>(&h);
}

__device__ __forceinline__ void mma_f16(float c[4], const uint32_t a[4], const uint32_t b[2]) {
    asm volatile(
        "mma.sync.aligned.m16n8k16.row.col.f32.f16.f16.f32 "
        "{%0,%1,%2,%3},{%4,%5,%6,%7},{%8,%9},{%0,%1,%2,%3};"
        : "+f"(c[0]), "+f"(c[1]), "+f"(c[2]), "+f"(c[3])
        : "r"(a[0]), "r"(a[1]), "r"(a[2]), "r"(a[3]), "r"(b[0]), "r"(b[1]));
}

// ldmatrix x4: lane l supplies the 16B row address of (matrix l>>3, row l&7).
__device__ __forceinline__ void ldsm_x4(uint32_t* r, uint32_t addr) {
    asm volatile("ldmatrix.sync.aligned.m8n8.x4.shared.b16 {%0,%1,%2,%3}, [%4];"
        : "=r"(r[0]), "=r"(r[1]), "=r"(r[2]), "=r"(r[3]) : "r"(addr));
}

__device__ __forceinline__ uint32_t smem_u32(const void* p) {
    return (uint32_t)__cvta_generic_to_shared(p);
}

__device__ __forceinline__ void cp_async16(void* sptr, const void* gptr) {
    uint32_t s = (uint32_t)__cvta_generic_to_shared(sptr);
    asm volatile("cp.async.cg.shared.global [%0], [%1], 16;" :: "r"(s), "l"(gptr));
}
__device__ __forceinline__ void cp_commit() { asm volatile("cp.async.commit_group;"); }
template<int N> __device__ __forceinline__ void cp_wait() {
    asm volatile("cp.async.wait_group %0;" :: "n"(N));
}

// ---------------------------------------------------------------------------
// Weight prepass: transpose + half-round all 4 weight matrices.
// ---------------------------------------------------------------------------
__global__ void wtrans_kernel(const float* __restrict__ w0, uint16_t* __restrict__ o0,
                              const float* __restrict__ w1, uint16_t* __restrict__ o1,
                              const float* __restrict__ w2, uint16_t* __restrict__ o2,
                              const float* __restrict__ w3, uint16_t* __restrict__ o3)
{
    __shared__ float tile[32][33];
    const float* W; uint16_t* O;
    switch (blockIdx.z) {
        case 0: W = w0; O = o0; break;
        case 1: W = w1; O = o1; break;
        case 2: W = w2; O = o2; break;
        default: W = w3; O = o3; break;
    }
    int bx = blockIdx.x * 32;   // n block
    int by = blockIdx.y * 32;   // k block
    int tx = threadIdx.x, ty = threadIdx.y;
    #pragma unroll
    for (int i = 0; i < 4; i++)
        tile[ty + 8*i][tx] = W[(size_t)(by + ty + 8*i) * D_MODEL + bx + tx];
    __syncthreads();
    #pragma unroll
    for (int i = 0; i < 4; i++) {
        __half h = __float2half_rn(tile[tx][ty + 8*i]);
        O[(size_t)(bx + ty + 8*i) * D_MODEL + by + tx] = *reinterpret_cast<uint16_t*>(&h);
    }
}

// ===========================================================================
// fp16 tensor-core GEMM: C[M,N] = A[M,K] @ Wt^T + bias  (Wt is half [N][K])
// BM=BN=128, BK=64 halves, 256 threads (8 warps, 64x32 warp tiles), 2-stage,
// ldmatrix fragment loads.
// CVT_A=1: A raw fp32, LDG->half->STS (2 waves).  CVT_A=0: A half, cp.async.
// REMAP=1: bias + half-round + head-split store; z==2 (V) stores TRANSPOSED.
// ===========================================================================
#define ALD 72   // halves per smem row (64 + 8 pad); 144 B
#define GEMM_STG (128 * ALD)                 // halves per stage per operand
#define GEMM_SMEM (4 * GEMM_STG * 2)         // 2 ops x 2 stages = 73728 B

template<int CVT_A, int REMAP>
__global__ __launch_bounds__(256, 2)
void gemm_h(const void* __restrict__ A0, const uint16_t* __restrict__ W0,
            const float* __restrict__ b0p, void* __restrict__ C0,
            const void* __restrict__ A1, const uint16_t* __restrict__ W1,
            const float* __restrict__ b1p, void* __restrict__ C1,
            const void* __restrict__ A2, const uint16_t* __restrict__ W2,
            const float* __restrict__ b2p, void* __restrict__ C2)
{
    const int K = D_MODEL, N = D_MODEL;
    extern __shared__ uint16_t smh[];
    uint16_t* As = smh;                 // [2][128][ALD]
    uint16_t* Bs = smh + 2 * GEMM_STG;  // [2][128][ALD]

    const void* Av; const uint16_t* Wt; const float* bias; void* Cv;
    const int zsel = blockIdx.z;
    switch (zsel) {
        case 0:  Av = A0; Wt = W0; bias = b0p; Cv = C0; break;
        case 1:  Av = A1; Wt = W1; bias = b1p; Cv = C1; break;
        default: Av = A2; Wt = W2; bias = b2p; Cv = C2; break;
    }
    const float*    Af = (const float*)Av;
    const uint16_t* Ah = (const uint16_t*)Av;

    const int t    = threadIdx.x;
    const int lane = t & 31;
    const int warp = t >> 5;
    const int g    = lane >> 2;
    const int tg   = lane & 3;
    const int wm   = (warp & 1) * 64;
    const int wn   = (warp >> 1) * 32;
    const int m0   = blockIdx.y * 128;
    const int n0   = blockIdx.x * 128;

    // ldmatrix lane geometry
    const int rowA = ((lane >> 3) & 1) * 8 + (lane & 7);
    const int kbA  = ((lane >> 4) & 1) * 16;          // byte bump for k+8
    const int rowB = ((lane >> 4) & 1) * 8 + (lane & 7);
    const int kbB  = ((lane >> 3) & 1) * 16;

    const uint32_t As_b = smem_u32(As);
    const uint32_t Bs_b = smem_u32(Bs);
    const uint32_t aLane = (uint32_t)(wm + rowA) * 144 + kbA;
    const uint32_t bLane = (uint32_t)(wn + rowB) * 144 + kbB;

    // cooperative load indices: 128 rows x 64 halves, 2 threads/row
    const int lrow = t >> 1;
    const int lhlf = (t & 1) * 32;

    float acc[4][4][4] = {};
    float4 areg[4];

    // ---- Prologue: chunk 0 into slot 0 ----
    if (CVT_A) {
        #pragma unroll
        for (int w = 0; w < 2; w++) {
            #pragma unroll
            for (int p = 0; p < 4; p++)
                areg[p] = *(const float4*)&Af[(size_t)(m0 + lrow) * K + lhlf + 16*w + 4*p];
            #pragma unroll
            for (int p = 0; p < 2; p++) {
                float4 u = areg[2*p], v = areg[2*p + 1];
                uint4 st;
                st.x = f2h2(u.x, u.y); st.y = f2h2(u.z, u.w);
                st.z = f2h2(v.x, v.y); st.w = f2h2(v.z, v.w);
                *(uint4*)&As[lrow * ALD + lhlf + 16*w + 8*p] = st;
            }
        }
    } else {
        #pragma unroll
        for (int p = 0; p < 4; p++)
            cp_async16(&As[lrow * ALD + lhlf + 8*p],
                       &Ah[(size_t)(m0 + lrow) * K + lhlf + 8*p]);
    }
    #pragma unroll
    for (int p = 0; p < 4; p++)
        cp_async16(&Bs[lrow * ALD + lhlf + 8*p],
                   &Wt[(size_t)(n0 + lrow) * K + lhlf + 8*p]);
    cp_commit();

    const int NCHUNK = K / 64;   // 16
    for (int c = 0; c < NCHUNK; c++) {
        cp_wait<0>();
        __syncthreads();
        const int s = c & 1;
        const bool more = (c + 1 < NCHUNK);
        const int kn = (c + 1) * 64;
        uint16_t* An = As + (s ^ 1) * GEMM_STG;
        if (more) {
            if (CVT_A) {
                #pragma unroll
                for (int p = 0; p < 4; p++)
                    areg[p] = *(const float4*)&Af[(size_t)(m0 + lrow) * K + kn + lhlf + 4*p];
            } else {
                #pragma unroll
                for (int p = 0; p < 4; p++)
                    cp_async16(&An[lrow * ALD + lhlf + 8*p],
                               &Ah[(size_t)(m0 + lrow) * K + kn + lhlf + 8*p]);
            }
            uint16_t* Bn = Bs + (s ^ 1) * GEMM_STG;
            #pragma unroll
            for (int p = 0; p < 4; p++)
                cp_async16(&Bn[lrow * ALD + lhlf + 8*p],
                           &Wt[(size_t)(n0 + lrow) * K + kn + lhlf + 8*p]);
            cp_commit();
        }
        const uint32_t aBase = As_b + s * (GEMM_STG * 2) + aLane;
        const uint32_t bBase = Bs_b + s * (GEMM_STG * 2) + bLane;
        #pragma unroll
        for (int ks = 0; ks < 4; ks++) {
            const uint32_t kby = ks * 32;
            uint32_t a[4][4], bp[2][4];
            #pragma unroll
            for (int mt = 0; mt < 4; mt++)
                ldsm_x4(a[mt], aBase + (uint32_t)mt * (16 * 144) + kby);
            #pragma unroll
            for (int p = 0; p < 2; p++)
                ldsm_x4(bp[p], bBase + (uint32_t)p * (16 * 144) + kby);
            #pragma unroll
            for (int mt = 0; mt < 4; mt++)
                #pragma unroll
                for (int nt = 0; nt < 4; nt++)
                    mma_f16(acc[mt][nt], a[mt], &bp[nt >> 1][(nt & 1) * 2]);
            if (ks == 1 && more && CVT_A) {
                // STS wave0, LDG wave1
                #pragma unroll
                for (int p = 0; p < 2; p++) {
                    float4 u = areg[2*p], v = areg[2*p + 1];
                    uint4 st;
                    st.x = f2h2(u.x, u.y); st.y = f2h2(u.z, u.w);
                    st.z = f2h2(v.x, v.y); st.w = f2h2(v.z, v.w);
                    *(uint4*)&An[lrow * ALD + lhlf + 8*p] = st;
                }
                #pragma unroll
                for (int p = 0; p < 4; p++)
                    areg[p] = *(const float4*)&Af[(size_t)(m0 + lrow) * K + kn + lhlf + 16 + 4*p];
            }
        }
        if (more && CVT_A) {
            #pragma unroll
            for (int p = 0; p < 2; p++) {
                float4 u = areg[2*p], v = areg[2*p + 1];
                uint4 st;
                st.x = f2h2(u.x, u.y); st.y = f2h2(u.z, u.w);
                st.z = f2h2(v.x, v.y); st.w = f2h2(v.z, v.w);
                *(uint4*)&An[lrow * ALD + lhlf + 16 + 8*p] = st;
            }
        }
    }

    // ---- Epilogue ----
    #pragma unroll
    for (int mt = 0; mt < 4; mt++) {
        #pragma unroll
        for (int nt = 0; nt < 4; nt++) {
            int n  = n0 + wn + nt * 8 + 2 * tg;
            float b0v = bias[n], b1v = bias[n + 1];
            #pragma unroll
            for (int half = 0; half < 2; half++) {
                int m = m0 + wm + mt * 16 + g + half * 8;
                float vx = acc[mt][nt][half*2 + 0] + b0v;
                float vy = acc[mt][nt][half*2 + 1] + b1v;
                if (REMAP) {
                    uint16_t* Ch = (uint16_t*)Cv;
                    int bb = m >> 11, srow = m & 2047;
                    int hh = n >> 6, dd = n & 63;
                    if (zsel == 2) {
                        __half h0 = __float2half_rn(vx), h1 = __float2half_rn(vy);
                        size_t base = ((size_t)(bb * NHEADS + hh)) * HDIM;
                        Ch[(base + dd)     * SEQ + srow] = *reinterpret_cast<uint16_t*>(&h0);
                        Ch[(base + dd + 1) * SEQ + srow] = *reinterpret_cast<uint16_t*>(&h1);
                    } else {
                        *(uint32_t*)&Ch[(((size_t)(bb * NHEADS + hh)) * SEQ + srow) * HDIM + dd]
                            = f2h2(vx, vy);
                    }
                } else {
                    float* Cf = (float*)Cv;
                    *(float2*)&Cf[(size_t)m * N + n] = make_float2(vx, vy);
                }
            }
        }
    }
}

// ---------------------------------------------------------------------------
// Causal flash attention, fp16 mma + ldmatrix, register-resident softmax.
// Q/K half [B,H,S,hd]; V half PRE-TRANSPOSED [B,H,hd,S]; ctx half [B,S,D].
// CTA = 256 threads (8 warps) on 128q x 64k tile; warp = 16q x 64k.
// ---------------------------------------------------------------------------
#define FLD 72   // halves per smem row (64 + 8 pad); 144 B
#define FLASH_SMEM ((128*FLD + 128*FLD + 2*64*FLD + 2*64*FLD) * 2)   // 73728 B

__global__ __launch_bounds__(256, 2)
void flash_h(const uint16_t* __restrict__ Q, const uint16_t* __restrict__ K,
             const uint16_t* __restrict__ V, uint16_t* __restrict__ ctx)
{
    extern __shared__ uint16_t smh[];
    uint16_t* Qs = smh;                    // [128][FLD]
    uint16_t* Ps = smh + 128 * FLD;        // [128][FLD]
    uint16_t* Ks = smh + 2 * 128 * FLD;    // [2][64][FLD]   Ks[k][d]
    uint16_t* Vs = Ks + 2 * 64 * FLD;      // [2][64][FLD]   Vs[d][k]

    const int t    = threadIdx.x;
    const int lane = t & 31;
    const int warp = t >> 5;
    const int g    = lane >> 2;
    const int tg   = lane & 3;
    const int wq   = warp * 16;
    const int qt   = blockIdx.x;
    const int bh   = blockIdx.y;
    const int q0   = qt * 128;
    const int kt_max = 2 * qt + 1;
    const float scl = 0.125f;

    // ldmatrix lane geometry
    const int rowA = ((lane >> 3) & 1) * 8 + (lane & 7);
    const int kbA  = ((lane >> 4) & 1) * 16;
    const int rowB = ((lane >> 4) & 1) * 8 + (lane & 7);
    const int kbB  = ((lane >> 3) & 1) * 16;

    const uint32_t smb  = smem_u32(smh);
    const uint32_t Qs_b = smb;
    const uint32_t Ps_b = smb + 128 * 144;
    const uint32_t Ks_b = smb + 2 * 128 * 144;
    const uint32_t Vs_b = Ks_b + 2 * 64 * 144;
    const uint32_t qa   = Qs_b + (uint32_t)(wq + rowA) * 144 + kbA;
    const uint32_t pa   = Ps_b + (uint32_t)(wq + rowA) * 144 + kbA;
    const uint32_t bLane = (uint32_t)rowB * 144 + kbB;

    // cooperative load indices
    const int qr = t >> 1, qc = (t & 1) * 32;        // Q: 128 rows, 2 thr/row
    const int kr = t >> 2, kc = (t & 3) * 16;        // K/V: 64 rows, 4 thr/row

    {
        const uint16_t* Qb = Q + ((size_t)bh * SEQ + q0) * HDIM;
        #pragma unroll
        for (int p = 0; p < 4; p++)
            cp_async16(&Qs[qr * FLD + qc + 8*p], &Qb[qr * HDIM + qc + 8*p]);
    }
    {
        const uint16_t* Kb = K + (size_t)bh * SEQ * HDIM;
        const uint16_t* Vb = V + (size_t)bh * HDIM * SEQ;
        #pragma unroll
        for (int p = 0; p < 2; p++) {
            cp_async16(&Ks[kr * FLD + kc + 8*p], &Kb[kr * HDIM + kc + 8*p]);
            cp_async16(&Vs[kr * FLD + kc + 8*p], &Vb[(size_t)kr * SEQ + kc + 8*p]);
        }
    }
    cp_commit();

    float m0r = -INFINITY, m1r = -INFINITY;
    float l0r = 0.f, l1r = 0.f;
    float o[8][4] = {};

    const int row0 = q0 + wq + g;
    const int row1 = row0 + 8;

    for (int kt = 0; kt <= kt_max; kt++) {
        cp_wait<0>();
        __syncthreads();
        const int s = kt & 1;
        if (kt < kt_max) {
            const int kn = (kt + 1) * 64;
            const uint16_t* Kb = K + ((size_t)bh * SEQ + kn) * HDIM;
            const uint16_t* Vb = V + (size_t)bh * HDIM * SEQ + kn;
            uint16_t* Kn = Ks + (s ^ 1) * 64 * FLD;
            uint16_t* Vn = Vs + (s ^ 1) * 64 * FLD;
            #pragma unroll
            for (int p = 0; p < 2; p++) {
                cp_async16(&Kn[kr * FLD + kc + 8*p], &Kb[kr * HDIM + kc + 8*p]);
                cp_async16(&Vn[kr * FLD + kc + 8*p], &Vb[(size_t)kr * SEQ + kc + 8*p]);
            }
            cp_commit();
        }
        const uint32_t Kc_b = Ks_b + s * (64 * 144) + bLane;
        const uint32_t Vc_b = Vs_b + s * (64 * 144) + bLane;
        const int k0 = kt * 64;

        // ---- S = Q K^T ----
        float sc[8][4] = {};
        #pragma unroll
        for (int ks = 0; ks < 4; ks++) {
            const uint32_t kby = ks * 32;
            uint32_t a[4], bp[4][4];
            ldsm_x4(a, qa + kby);
            #pragma unroll
            for (int p = 0; p < 4; p++)
                ldsm_x4(bp[p], Kc_b + (uint32_t)p * (16 * 144) + kby);
            #pragma unroll
            for (int nt = 0; nt < 8; nt++)
                mma_f16(sc[nt], a, &bp[nt >> 1][(nt & 1) * 2]);
        }

        // ---- scale + causal mask ----
        if (k0 + 63 > row0) {
            #pragma unroll
            for (int nt = 0; nt < 8; nt++) {
                int c = k0 + nt * 8 + 2 * tg;
                sc[nt][0] = (c     > row0) ? -INFINITY : sc[nt][0] * scl;
                sc[nt][1] = (c + 1 > row0) ? -INFINITY : sc[nt][1] * scl;
                sc[nt][2] = (c     > row1) ? -INFINITY : sc[nt][2] * scl;
                sc[nt][3] = (c + 1 > row1) ? -INFINITY : sc[nt][3] * scl;
            }
        } else {
            #pragma unroll
            for (int nt = 0; nt < 8; nt++)
                #pragma unroll
                for (int i = 0; i < 4; i++) sc[nt][i] *= scl;
        }

        // ---- row max (registers + quad shuffle) ----
        float mx0 = -INFINITY, mx1 = -INFINITY;
        #pragma unroll
        for (int nt = 0; nt < 8; nt++) {
            mx0 = fmaxf(mx0, fmaxf(sc[nt][0], sc[nt][1]));
            mx1 = fmaxf(mx1, fmaxf(sc[nt][2], sc[nt][3]));
        }
        mx0 = fmaxf(mx0, __shfl_xor_sync(0xffffffff, mx0, 1));
        mx0 = fmaxf(mx0, __shfl_xor_sync(0xffffffff, mx0, 2));
        mx1 = fmaxf(mx1, __shfl_xor_sync(0xffffffff, mx1, 1));
        mx1 = fmaxf(mx1, __shfl_xor_sync(0xffffffff, mx1, 2));

        float mn0 = fmaxf(m0r, mx0), mn1 = fmaxf(m1r, mx1);
        float al0 = __expf(m0r - mn0), al1 = __expf(m1r - mn1);
        m0r = mn0; m1r = mn1;

        // ---- exp (half-rounded), row sums over rounded values, write P ----
        float s0 = 0.f, s1 = 0.f;
        #pragma unroll
        for (int nt = 0; nt < 8; nt++) {
            __half2 hp0 = __floats2half2_rn(__expf(sc[nt][0] - mn0), __expf(sc[nt][1] - mn0));
            __half2 hp1 = __floats2half2_rn(__expf(sc[nt][2] - mn1), __expf(sc[nt][3] - mn1));
            float2 r0 = __half22float2(hp0);
            float2 r1 = __half22float2(hp1);
            s0 += r0.x + r0.y;
            s1 += r1.x + r1.y;
            int c = nt * 8 + 2 * tg;
            *(uint32_t*)&Ps[(wq + g) * FLD + c]     = *reinterpret_cast<uint32_t*>(&hp0);
            *(uint32_t*)&Ps[(wq + g + 8) * FLD + c] = *reinterpret_cast<uint32_t*>(&hp1);
        }
        s0 += __shfl_xor_sync(0xffffffff, s0, 1);
        s0 += __shfl_xor_sync(0xffffffff, s0, 2);
        s1 += __shfl_xor_sync(0xffffffff, s1, 1);
        s1 += __shfl_xor_sync(0xffffffff, s1, 2);
        l0r = l0r * al0 + s0;
        l1r = l1r * al1 + s1;
        #pragma unroll
        for (int nt = 0; nt < 8; nt++) {
            o[nt][0] *= al0; o[nt][1] *= al0;
            o[nt][2] *= al1; o[nt][3] *= al1;
        }
        __syncwarp();   // P tile is warp-private

        // ---- O += P V ----
        #pragma unroll
        for (int ks = 0; ks < 4; ks++) {
            const uint32_t kby = ks * 32;
            uint32_t a[4], bp[4][4];
            ldsm_x4(a, pa + kby);
            #pragma unroll
            for (int p = 0; p < 4; p++)
                ldsm_x4(bp[p], Vc_b + (uint32_t)p * (16 * 144) + kby);
            #pragma unroll
            for (int nt = 0; nt < 8; nt++)
                mma_f16(o[nt], a, &bp[nt >> 1][(nt & 1) * 2]);
        }
    }

    // Epilogue: normalize, half-round, write ctx [B,S,D] half
    const int bb = bh >> 4;
    const int hh = bh & 15;
    const float il0 = 1.f / l0r, il1 = 1.f / l1r;
    #pragma unroll
    for (int nt = 0; nt < 8; nt++) {
        int d = nt * 8 + 2 * tg;
        *(uint32_t*)&ctx[((size_t)bb * SEQ + row0) * D_MODEL + hh * HDIM + d]
            = f2h2(o[nt][0] * il0, o[nt][1] * il0);
        *(uint32_t*)&ctx[((size_t)bb * SEQ + row1) * D_MODEL + hh * HDIM + d]
            = f2h2(o[nt][2] * il1, o[nt][3] * il1);
    }
}

// ---------------------------------------------------------------------------
extern "C" void kernel_launch(void* const* d_in, const int* in_sizes, int n_in,
                              void* d_out, int out_size)
{
    const float* in_q = (const float*)d_in[0];
    const float* in_k = (const float*)d_in[1];
    const float* in_v = (const float*)d_in[2];
    const float* Wq   = (const float*)d_in[3];
    const float* bq   = (const float*)d_in[4];
    const float* Wk   = (const float*)d_in[5];
    const float* bk   = (const float*)d_in[6];
    const float* Wv   = (const float*)d_in[7];
    const float* bv   = (const float*)d_in[8];
    const float* Wo   = (const float*)d_in[9];
    const float* bo   = (const float*)d_in[10];
    float* out = (float*)d_out;

    uint16_t *gq, *gk, *gv, *gc, *wq, *wk, *wv, *wo;
    cudaGetSymbolAddress((void**)&gq, g_Q);
    cudaGetSymbolAddress((void**)&gk, g_K);
    cudaGetSymbolAddress((void**)&gv, g_V);
    cudaGetSymbolAddress((void**)&gc, g_C);
    cudaGetSymbolAddress((void**)&wq, g_Wq);
    cudaGetSymbolAddress((void**)&wk, g_Wk);
    cudaGetSymbolAddress((void**)&wv, g_Wv);
    cudaGetSymbolAddress((void**)&wo, g_Wo);

    static int attr_set = 0;
    if (!attr_set) {
        cudaFuncSetAttribute(gemm_h<1,1>, cudaFuncAttributeMaxDynamicSharedMemorySize, GEMM_SMEM);
        cudaFuncSetAttribute(gemm_h<0,0>, cudaFuncAttributeMaxDynamicSharedMemorySize, GEMM_SMEM);
        cudaFuncSetAttribute(flash_h,     cudaFuncAttributeMaxDynamicSharedMemorySize, FLASH_SMEM);
        attr_set = 1;
    }

    // Weight prepass: transpose + half-round, one launch
    dim3 wt_grid(32, 32, 4);
    wtrans_kernel<<<wt_grid, dim3(32, 8)>>>(Wq, wq, Wk, wk, Wv, wv, Wo, wo);

    // Fused QKV projections, one launch (z selects problem)
    dim3 qkv_grid(D_MODEL / 128, MROWS / 128, 3);   // (8, 64, 3)
    gemm_h<1,1><<<qkv_grid, 256, GEMM_SMEM>>>(in_q, wq, bq, gq,
                                              in_k, wk, bk, gk,
                                              in_v, wv, bv, gv);

    dim3 attn_grid(SEQ / 128, BATCH * NHEADS);      // (16, 64)
    flash_h<<<attn_grid, 256, FLASH_SMEM>>>(gq, gk, gv, gc);

    // O-projection: A = half ctx, output fp32 + bias
    dim3 o_grid(D_MODEL / 128, MROWS / 128, 1);     // (8, 64)
    gemm_h<0,0><<<o_grid, 256, GEMM_SMEM>>>(gc, wo, bo, out,
                                            gc, wo, bo, out,
                                            gc, wo, bo, out);
}

// round 12
// speedup vs baseline: 1.1034x; 1.1034x over previous
#include <cuda_runtime.h>
#include <cuda_fp16.h>
#include <math.h>
#include <stdint.h>

#define D_MODEL 1024
#define NHEADS  16
#define HDIM    64
#define BATCH   4
#define SEQ     2048
#define MROWS   (BATCH*SEQ)   // 8192

// Scratch (device globals — no allocations allowed). Halves stored as uint16_t.
__device__ uint16_t g_Q[(size_t)MROWS * D_MODEL];   // [B,H,S,hd] half
__device__ uint16_t g_K[(size_t)MROWS * D_MODEL];   // [B,H,S,hd] half
__device__ uint16_t g_V[(size_t)MROWS * D_MODEL];   // [B,H,hd,S] half (pre-transposed!)
__device__ uint16_t g_C[(size_t)MROWS * D_MODEL];   // [B,S,D]    half
// half activations (pre-rounded)
__device__ uint16_t g_Aq[(size_t)MROWS * D_MODEL];
__device__ uint16_t g_Ak[(size_t)MROWS * D_MODEL];
__device__ uint16_t g_Av[(size_t)MROWS * D_MODEL];
// half TRANSPOSED weights: Wt[n][k] = half(W[k][n])
__device__ uint16_t g_Wq[(size_t)D_MODEL * D_MODEL];
__device__ uint16_t g_Wk[(size_t)D_MODEL * D_MODEL];
__device__ uint16_t g_Wv[(size_t)D_MODEL * D_MODEL];
__device__ uint16_t g_Wo[(size_t)D_MODEL * D_MODEL];

__device__ __forceinline__ uint32_t f2h2(float a, float b) {
    __half2 h = __floats2half2_rn(a, b);
    return *reinterpret_cast<uint32_t*>(&h);
}

__device__ __forceinline__ void mma_f16(float c[4], const uint32_t a[4], const uint32_t b[2]) {
    asm volatile(
        "mma.sync.aligned.m16n8k16.row.col.f32.f16.f16.f32 "
        "{%0,%1,%2,%3},{%4,%5,%6,%7},{%8,%9},{%0,%1,%2,%3};"
        : "+f"(c[0]), "+f"(c[1]), "+f"(c[2]), "+f"(c[3])
        : "r"(a[0]), "r"(a[1]), "r"(a[2]), "r"(a[3]), "r"(b[0]), "r"(b[1]));
}

__device__ __forceinline__ void cp_async16(void* sptr, const void* gptr) {
    uint32_t s = (uint32_t)__cvta_generic_to_shared(sptr);
    asm volatile("cp.async.cg.shared.global [%0], [%1], 16;" :: "r"(s), "l"(gptr));
}
__device__ __forceinline__ void cp_commit() { asm volatile("cp.async.commit_group;"); }
template<int N> __device__ __forceinline__ void cp_wait() {
    asm volatile("cp.async.wait_group %0;" :: "n"(N));
}

// ---------------------------------------------------------------------------
// Activation prepass: fp32 -> half, 3 tensors (grid.z selects). 8 floats/thread.
// ---------------------------------------------------------------------------
__global__ void acvt_kernel(const float4* __restrict__ a0, uint4* __restrict__ o0,
                            const float4* __restrict__ a1, uint4* __restrict__ o1,
                            const float4* __restrict__ a2, uint4* __restrict__ o2,
                            int n8)
{
    const float4* in; uint4* out;
    switch (blockIdx.z) {
        case 0: in = a0; out = o0; break;
        case 1: in = a1; out = o1; break;
        default: in = a2; out = o2; break;
    }
    int i = blockIdx.x * blockDim.x + threadIdx.x;
    if (i < n8) {
        float4 u = in[2*i], v = in[2*i + 1];
        uint4 st;
        st.x = f2h2(u.x, u.y); st.y = f2h2(u.z, u.w);
        st.z = f2h2(v.x, v.y); st.w = f2h2(v.z, v.w);
        out[i] = st;
    }
}

// ---------------------------------------------------------------------------
// Weight prepass: transpose + half-round all 4 weight matrices.
// ---------------------------------------------------------------------------
__global__ void wtrans_kernel(const float* __restrict__ w0, uint16_t* __restrict__ o0,
                              const float* __restrict__ w1, uint16_t* __restrict__ o1,
                              const float* __restrict__ w2, uint16_t* __restrict__ o2,
                              const float* __restrict__ w3, uint16_t* __restrict__ o3)
{
    __shared__ float tile[32][33];
    const float* W; uint16_t* O;
    switch (blockIdx.z) {
        case 0: W = w0; O = o0; break;
        case 1: W = w1; O = o1; break;
        case 2: W = w2; O = o2; break;
        default: W = w3; O = o3; break;
    }
    int bx = blockIdx.x * 32;   // n block
    int by = blockIdx.y * 32;   // k block
    int tx = threadIdx.x, ty = threadIdx.y;
    #pragma unroll
    for (int i = 0; i < 4; i++)
        tile[ty + 8*i][tx] = W[(size_t)(by + ty + 8*i) * D_MODEL + bx + tx];
    __syncthreads();
    #pragma unroll
    for (int i = 0; i < 4; i++) {
        __half h = __float2half_rn(tile[tx][ty + 8*i]);
        O[(size_t)(bx + ty + 8*i) * D_MODEL + by + tx] = *reinterpret_cast<uint16_t*>(&h);
    }
}

// ===========================================================================
// fp16 tensor-core GEMM: C[M,N] = A[M,K] @ Wt^T + bias  (A, Wt both half)
// BM=BN=128, BK=32 halves, 256 threads (8 warps, 64x32 warp tiles),
// 3-stage cp.async pipeline with cp_wait<1>.
// REMAP=1: bias + half-round + head-split store; z==2 (V) stores TRANSPOSED.
// ===========================================================================
#define ALD 40                    // halves per smem row (32 + 8 pad); 80 B
#define STG (128 * ALD)           // halves per operand per stage
#define NSTG 3
#define GEMM_SMEM (2 * NSTG * STG * 2)   // 61440 B

template<int REMAP>
__global__ __launch_bounds__(256, 2)
void gemm_h(const uint16_t* __restrict__ A0, const uint16_t* __restrict__ W0,
            const float* __restrict__ b0p, void* __restrict__ C0,
            const uint16_t* __restrict__ A1, const uint16_t* __restrict__ W1,
            const float* __restrict__ b1p, void* __restrict__ C1,
            const uint16_t* __restrict__ A2, const uint16_t* __restrict__ W2,
            const float* __restrict__ b2p, void* __restrict__ C2)
{
    const int K = D_MODEL, N = D_MODEL;
    extern __shared__ uint16_t smh[];
    uint16_t* As = smh;               // [NSTG][128][ALD]
    uint16_t* Bs = smh + NSTG * STG;  // [NSTG][128][ALD]

    const uint16_t *Ah, *Wt; const float* bias; void* Cv;
    const int zsel = blockIdx.z;
    switch (zsel) {
        case 0:  Ah = A0; Wt = W0; bias = b0p; Cv = C0; break;
        case 1:  Ah = A1; Wt = W1; bias = b1p; Cv = C1; break;
        default: Ah = A2; Wt = W2; bias = b2p; Cv = C2; break;
    }

    const int t    = threadIdx.x;
    const int lane = t & 31;
    const int warp = t >> 5;
    const int g    = lane >> 2;
    const int tg   = lane & 3;
    const int wm   = (warp & 1) * 64;
    const int wn   = (warp >> 1) * 32;
    const int m0   = blockIdx.y * 128;
    const int n0   = blockIdx.x * 128;

    // cooperative load: 128 rows x 32 halves, 2 threads/row, 16 halves each
    const int lrow = t >> 1;
    const int lhlf = (t & 1) * 16;

    float acc[4][4][4] = {};

    // ---- Prologue: stages 0, 1 ----
    #pragma unroll
    for (int st = 0; st < 2; st++) {
        uint16_t* Ad = As + st * STG;
        uint16_t* Bd = Bs + st * STG;
        #pragma unroll
        for (int p = 0; p < 2; p++) {
            cp_async16(&Ad[lrow * ALD + lhlf + 8*p],
                       &Ah[(size_t)(m0 + lrow) * K + st * 32 + lhlf + 8*p]);
            cp_async16(&Bd[lrow * ALD + lhlf + 8*p],
                       &Wt[(size_t)(n0 + lrow) * K + st * 32 + lhlf + 8*p]);
        }
        cp_commit();
    }

    const int NCHUNK = K / 32;   // 32
    for (int c = 0; c < NCHUNK; c++) {
        if (c + 1 < NCHUNK) cp_wait<1>(); else cp_wait<0>();
        __syncthreads();
        const int s = c % NSTG;
        if (c + 2 < NCHUNK) {
            const int sn = (c + 2) % NSTG;
            const int kn = (c + 2) * 32;
            uint16_t* Ad = As + sn * STG;
            uint16_t* Bd = Bs + sn * STG;
            #pragma unroll
            for (int p = 0; p < 2; p++) {
                cp_async16(&Ad[lrow * ALD + lhlf + 8*p],
                           &Ah[(size_t)(m0 + lrow) * K + kn + lhlf + 8*p]);
                cp_async16(&Bd[lrow * ALD + lhlf + 8*p],
                           &Wt[(size_t)(n0 + lrow) * K + kn + lhlf + 8*p]);
            }
            cp_commit();
        }
        const uint16_t* Ac = As + s * STG;
        const uint16_t* Bc = Bs + s * STG;
        #pragma unroll
        for (int ks = 0; ks < 2; ks++) {
            const int kk = ks * 16 + 2 * tg;
            uint32_t a[4][4], b[4][2];
            #pragma unroll
            for (int mt = 0; mt < 4; mt++) {
                int m = wm + mt * 16 + g;
                a[mt][0] = *(const uint32_t*)&Ac[m * ALD + kk];
                a[mt][1] = *(const uint32_t*)&Ac[(m + 8) * ALD + kk];
                a[mt][2] = *(const uint32_t*)&Ac[m * ALD + kk + 8];
                a[mt][3] = *(const uint32_t*)&Ac[(m + 8) * ALD + kk + 8];
            }
            #pragma unroll
            for (int nt = 0; nt < 4; nt++) {
                int n = wn + nt * 8 + g;
                b[nt][0] = *(const uint32_t*)&Bc[n * ALD + kk];
                b[nt][1] = *(const uint32_t*)&Bc[n * ALD + kk + 8];
            }
            #pragma unroll
            for (int mt = 0; mt < 4; mt++)
                #pragma unroll
                for (int nt = 0; nt < 4; nt++)
                    mma_f16(acc[mt][nt], a[mt], b[nt]);
        }
    }

    // ---- Epilogue ----
    #pragma unroll
    for (int mt = 0; mt < 4; mt++) {
        #pragma unroll
        for (int nt = 0; nt < 4; nt++) {
            int n  = n0 + wn + nt * 8 + 2 * tg;
            float b0v = bias[n], b1v = bias[n + 1];
            #pragma unroll
            for (int half = 0; half < 2; half++) {
                int m = m0 + wm + mt * 16 + g + half * 8;
                float vx = acc[mt][nt][half*2 + 0] + b0v;
                float vy = acc[mt][nt][half*2 + 1] + b1v;
                if (REMAP) {
                    uint16_t* Ch = (uint16_t*)Cv;
                    int bb = m >> 11, srow = m & 2047;
                    int hh = n >> 6, dd = n & 63;
                    if (zsel == 2) {
                        // V: store transposed [B,H,hd,S]
                        __half h0 = __float2half_rn(vx), h1 = __float2half_rn(vy);
                        size_t base = ((size_t)(bb * NHEADS + hh)) * HDIM;
                        Ch[(base + dd)     * SEQ + srow] = *reinterpret_cast<uint16_t*>(&h0);
                        Ch[(base + dd + 1) * SEQ + srow] = *reinterpret_cast<uint16_t*>(&h1);
                    } else {
                        *(uint32_t*)&Ch[(((size_t)(bb * NHEADS + hh)) * SEQ + srow) * HDIM + dd]
                            = f2h2(vx, vy);
                    }
                } else {
                    float* Cf = (float*)Cv;
                    *(float2*)&Cf[(size_t)m * N + n] = make_float2(vx, vy);
                }
            }
        }
    }
}

// ---------------------------------------------------------------------------
// Causal flash attention, fp16 mma, register-resident softmax. (R9 form)
// Q/K half [B,H,S,hd]; V half PRE-TRANSPOSED [B,H,hd,S]; ctx half [B,S,D].
// CTA = 256 threads (8 warps) on 128q x 64k tile; warp = 16q x 64k.
// ---------------------------------------------------------------------------
#define FLD 72   // halves per smem row (64 + 8 pad); 144 B
#define FLASH_SMEM ((128*FLD + 128*FLD + 2*64*FLD + 2*64*FLD) * 2)   // 73728 B

__global__ __launch_bounds__(256, 2)
void flash_h(const uint16_t* __restrict__ Q, const uint16_t* __restrict__ K,
             const uint16_t* __restrict__ V, uint16_t* __restrict__ ctx)
{
    extern __shared__ uint16_t smh[];
    uint16_t* Qs = smh;                    // [128][FLD]
    uint16_t* Ps = smh + 128 * FLD;        // [128][FLD]
    uint16_t* Ks = smh + 2 * 128 * FLD;    // [2][64][FLD]   Ks[k][d]
    uint16_t* Vs = Ks + 2 * 64 * FLD;      // [2][64][FLD]   Vs[d][k]

    const int t    = threadIdx.x;
    const int lane = t & 31;
    const int warp = t >> 5;
    const int g    = lane >> 2;
    const int tg   = lane & 3;
    const int wq   = warp * 16;
    const int qt   = blockIdx.x;
    const int bh   = blockIdx.y;
    const int q0   = qt * 128;
    const int kt_max = 2 * qt + 1;
    const float scl = 0.125f;

    // cooperative load indices
    const int qr = t >> 1, qc = (t & 1) * 32;        // Q: 128 rows, 2 thr/row
    const int kr = t >> 2, kc = (t & 3) * 16;        // K/V: 64 rows, 4 thr/row

    {
        const uint16_t* Qb = Q + ((size_t)bh * SEQ + q0) * HDIM;
        #pragma unroll
        for (int p = 0; p < 4; p++)
            cp_async16(&Qs[qr * FLD + qc + 8*p], &Qb[qr * HDIM + qc + 8*p]);
    }
    {
        const uint16_t* Kb = K + (size_t)bh * SEQ * HDIM;
        const uint16_t* Vb = V + (size_t)bh * HDIM * SEQ;
        #pragma unroll
        for (int p = 0; p < 2; p++) {
            cp_async16(&Ks[kr * FLD + kc + 8*p], &Kb[kr * HDIM + kc + 8*p]);
            cp_async16(&Vs[kr * FLD + kc + 8*p], &Vb[(size_t)kr * SEQ + kc + 8*p]);
        }
    }
    cp_commit();

    float m0r = -INFINITY, m1r = -INFINITY;
    float l0r = 0.f, l1r = 0.f;
    float o[8][4] = {};

    const int row0 = q0 + wq + g;
    const int row1 = row0 + 8;

    for (int kt = 0; kt <= kt_max; kt++) {
        cp_wait<0>();
        __syncthreads();
        const int s = kt & 1;
        if (kt < kt_max) {
            const int kn = (kt + 1) * 64;
            const uint16_t* Kb = K + ((size_t)bh * SEQ + kn) * HDIM;
            const uint16_t* Vb = V + (size_t)bh * HDIM * SEQ + kn;
            uint16_t* Kn = Ks + (s ^ 1) * 64 * FLD;
            uint16_t* Vn = Vs + (s ^ 1) * 64 * FLD;
            #pragma unroll
            for (int p = 0; p < 2; p++) {
                cp_async16(&Kn[kr * FLD + kc + 8*p], &Kb[kr * HDIM + kc + 8*p]);
                cp_async16(&Vn[kr * FLD + kc + 8*p], &Vb[(size_t)kr * SEQ + kc + 8*p]);
            }
            cp_commit();
        }
        const uint16_t* Kc = Ks + s * 64 * FLD;
        const uint16_t* Vc = Vs + s * 64 * FLD;
        const int k0 = kt * 64;

        // ---- S = Q K^T ----
        float sc[8][4] = {};
        #pragma unroll
        for (int ks = 0; ks < 4; ks++) {
            const int kk = ks * 16 + 2 * tg;
            uint32_t a[4], b[8][2];
            a[0] = *(const uint32_t*)&Qs[(wq + g) * FLD + kk];
            a[1] = *(const uint32_t*)&Qs[(wq + g + 8) * FLD + kk];
            a[2] = *(const uint32_t*)&Qs[(wq + g) * FLD + kk + 8];
            a[3] = *(const uint32_t*)&Qs[(wq + g + 8) * FLD + kk + 8];
            #pragma unroll
            for (int nt = 0; nt < 8; nt++) {
                int n = nt * 8 + g;
                b[nt][0] = *(const uint32_t*)&Kc[n * FLD + kk];
                b[nt][1] = *(const uint32_t*)&Kc[n * FLD + kk + 8];
            }
            #pragma unroll
            for (int nt = 0; nt < 8; nt++)
                mma_f16(sc[nt], a, b[nt]);
        }

        // ---- scale + causal mask ----
        if (k0 + 63 > row0) {
            #pragma unroll
            for (int nt = 0; nt < 8; nt++) {
                int c = k0 + nt * 8 + 2 * tg;
                sc[nt][0] = (c     > row0) ? -INFINITY : sc[nt][0] * scl;
                sc[nt][1] = (c + 1 > row0) ? -INFINITY : sc[nt][1] * scl;
                sc[nt][2] = (c     > row1) ? -INFINITY : sc[nt][2] * scl;
                sc[nt][3] = (c + 1 > row1) ? -INFINITY : sc[nt][3] * scl;
            }
        } else {
            #pragma unroll
            for (int nt = 0; nt < 8; nt++)
                #pragma unroll
                for (int i = 0; i < 4; i++) sc[nt][i] *= scl;
        }

        // ---- row max (registers + quad shuffle) ----
        float mx0 = -INFINITY, mx1 = -INFINITY;
        #pragma unroll
        for (int nt = 0; nt < 8; nt++) {
            mx0 = fmaxf(mx0, fmaxf(sc[nt][0], sc[nt][1]));
            mx1 = fmaxf(mx1, fmaxf(sc[nt][2], sc[nt][3]));
        }
        mx0 = fmaxf(mx0, __shfl_xor_sync(0xffffffff, mx0, 1));
        mx0 = fmaxf(mx0, __shfl_xor_sync(0xffffffff, mx0, 2));
        mx1 = fmaxf(mx1, __shfl_xor_sync(0xffffffff, mx1, 1));
        mx1 = fmaxf(mx1, __shfl_xor_sync(0xffffffff, mx1, 2));

        float mn0 = fmaxf(m0r, mx0), mn1 = fmaxf(m1r, mx1);
        float al0 = __expf(m0r - mn0), al1 = __expf(m1r - mn1);
        m0r = mn0; m1r = mn1;

        // ---- exp (half-rounded), row sums over rounded values, write P ----
        float s0 = 0.f, s1 = 0.f;
        #pragma unroll
        for (int nt = 0; nt < 8; nt++) {
            __half2 hp0 = __floats2half2_rn(__expf(sc[nt][0] - mn0), __expf(sc[nt][1] - mn0));
            __half2 hp1 = __floats2half2_rn(__expf(sc[nt][2] - mn1), __expf(sc[nt][3] - mn1));
            float2 r0 = __half22float2(hp0);
            float2 r1 = __half22float2(hp1);
            s0 += r0.x + r0.y;
            s1 += r1.x + r1.y;
            int c = nt * 8 + 2 * tg;
            *(uint32_t*)&Ps[(wq + g) * FLD + c]     = *reinterpret_cast<uint32_t*>(&hp0);
            *(uint32_t*)&Ps[(wq + g + 8) * FLD + c] = *reinterpret_cast<uint32_t*>(&hp1);
        }
        s0 += __shfl_xor_sync(0xffffffff, s0, 1);
        s0 += __shfl_xor_sync(0xffffffff, s0, 2);
        s1 += __shfl_xor_sync(0xffffffff, s1, 1);
        s1 += __shfl_xor_sync(0xffffffff, s1, 2);
        l0r = l0r * al0 + s0;
        l1r = l1r * al1 + s1;
        #pragma unroll
        for (int nt = 0; nt < 8; nt++) {
            o[nt][0] *= al0; o[nt][1] *= al0;
            o[nt][2] *= al1; o[nt][3] *= al1;
        }
        __syncwarp();   // P tile is warp-private

        // ---- O += P V ----
        #pragma unroll
        for (int ks = 0; ks < 4; ks++) {
            const int kk = ks * 16 + 2 * tg;
            uint32_t a[4], b[8][2];
            a[0] = *(const uint32_t*)&Ps[(wq + g) * FLD + kk];
            a[1] = *(const uint32_t*)&Ps[(wq + g + 8) * FLD + kk];
            a[2] = *(const uint32_t*)&Ps[(wq + g) * FLD + kk + 8];
            a[3] = *(const uint32_t*)&Ps[(wq + g + 8) * FLD + kk + 8];
            #pragma unroll
            for (int nt = 0; nt < 8; nt++) {
                int d = nt * 8 + g;
                b[nt][0] = *(const uint32_t*)&Vc[d * FLD + kk];
                b[nt][1] = *(const uint32_t*)&Vc[d * FLD + kk + 8];
            }
            #pragma unroll
            for (int nt = 0; nt < 8; nt++)
                mma_f16(o[nt], a, b[nt]);
        }
    }

    // Epilogue: normalize, half-round, write ctx [B,S,D] half
    const int bb = bh >> 4;
    const int hh = bh & 15;
    const float il0 = 1.f / l0r, il1 = 1.f / l1r;
    #pragma unroll
    for (int nt = 0; nt < 8; nt++) {
        int d = nt * 8 + 2 * tg;
        *(uint32_t*)&ctx[((size_t)bb * SEQ + row0) * D_MODEL + hh * HDIM + d]
            = f2h2(o[nt][0] * il0, o[nt][1] * il0);
        *(uint32_t*)&ctx[((size_t)bb * SEQ + row1) * D_MODEL + hh * HDIM + d]
            = f2h2(o[nt][2] * il1, o[nt][3] * il1);
    }
}

// ---------------------------------------------------------------------------
extern "C" void kernel_launch(void* const* d_in, const int* in_sizes, int n_in,
                              void* d_out, int out_size)
{
    const float* in_q = (const float*)d_in[0];
    const float* in_k = (const float*)d_in[1];
    const float* in_v = (const float*)d_in[2];
    const float* Wq   = (const float*)d_in[3];
    const float* bq   = (const float*)d_in[4];
    const float* Wk   = (const float*)d_in[5];
    const float* bk   = (const float*)d_in[6];
    const float* Wv   = (const float*)d_in[7];
    const float* bv   = (const float*)d_in[8];
    const float* Wo   = (const float*)d_in[9];
    const float* bo   = (const float*)d_in[10];
    float* out = (float*)d_out;

    uint16_t *gq, *gk, *gv, *gc, *aq, *ak, *av, *wq, *wk, *wv, *wo;
    cudaGetSymbolAddress((void**)&gq, g_Q);
    cudaGetSymbolAddress((void**)&gk, g_K);
    cudaGetSymbolAddress((void**)&gv, g_V);
    cudaGetSymbolAddress((void**)&gc, g_C);
    cudaGetSymbolAddress((void**)&aq, g_Aq);
    cudaGetSymbolAddress((void**)&ak, g_Ak);
    cudaGetSymbolAddress((void**)&av, g_Av);
    cudaGetSymbolAddress((void**)&wq, g_Wq);
    cudaGetSymbolAddress((void**)&wk, g_Wk);
    cudaGetSymbolAddress((void**)&wv, g_Wv);
    cudaGetSymbolAddress((void**)&wo, g_Wo);

    static int attr_set = 0;
    if (!attr_set) {
        cudaFuncSetAttribute(gemm_h<1>, cudaFuncAttributeMaxDynamicSharedMemorySize, GEMM_SMEM);
        cudaFuncSetAttribute(gemm_h<0>, cudaFuncAttributeMaxDynamicSharedMemorySize, GEMM_SMEM);
        cudaFuncSetAttribute(flash_h,   cudaFuncAttributeMaxDynamicSharedMemorySize, FLASH_SMEM);
        attr_set = 1;
    }

    // Prepass: weights (transpose+round) and activations (round), 2 launches
    dim3 wt_grid(32, 32, 4);
    wtrans_kernel<<<wt_grid, dim3(32, 8)>>>(Wq, wq, Wk, wk, Wv, wv, Wo, wo);
    const int n8 = MROWS * D_MODEL / 8;   // 1M
    dim3 ac_grid((n8 + 255)/256, 1, 3);
    acvt_kernel<<<ac_grid, 256>>>((const float4*)in_q, (uint4*)aq,
                                  (const float4*)in_k, (uint4*)ak,
                                  (const float4*)in_v, (uint4*)av, n8);

    // Fused QKV projections, one launch (z selects problem)
    dim3 qkv_grid(D_MODEL / 128, MROWS / 128, 3);   // (8, 64, 3)
    gemm_h<1><<<qkv_grid, 256, GEMM_SMEM>>>(aq, wq, bq, gq,
                                            ak, wk, bk, gk,
                                            av, wv, bv, gv);

    dim3 attn_grid(SEQ / 128, BATCH * NHEADS);      // (16, 64)
    flash_h<<<attn_grid, 256, FLASH_SMEM>>>(gq, gk, gv, gc);

    // O-projection: A = half ctx, output fp32 + bias
    dim3 o_grid(D_MODEL / 128, MROWS / 128, 1);     // (8, 64)
    gemm_h<0><<<o_grid, 256, GEMM_SMEM>>>(gc, wo, bo, out,
                                          gc, wo, bo, out,
                                          gc, wo, bo, out);
}

// round 13
// speedup vs baseline: 1.1085x; 1.0046x over previous
#include <cuda_runtime.h>
#include <cuda_fp16.h>
#include <math.h>
#include <stdint.h>

#define D_MODEL 1024
#define NHEADS  16
#define HDIM    64
#define BATCH   4
#define SEQ     2048
#define MROWS   (BATCH*SEQ)   // 8192

// Scratch (device globals — no allocations allowed). Halves stored as uint16_t.
__device__ uint16_t g_Q[(size_t)MROWS * D_MODEL];   // [B,H,S,hd] half, PRE-SCALED by 0.125
__device__ uint16_t g_K[(size_t)MROWS * D_MODEL];   // [B,H,S,hd] half
__device__ uint16_t g_V[(size_t)MROWS * D_MODEL];   // [B,H,hd,S] half (pre-transposed!)
__device__ uint16_t g_C[(size_t)MROWS * D_MODEL];   // [B,S,D]    half
// half activations (pre-rounded)
__device__ uint16_t g_Aq[(size_t)MROWS * D_MODEL];
__device__ uint16_t g_Ak[(size_t)MROWS * D_MODEL];
__device__ uint16_t g_Av[(size_t)MROWS * D_MODEL];
// half TRANSPOSED weights: Wt[n][k] = half(W[k][n])
__device__ uint16_t g_Wq[(size_t)D_MODEL * D_MODEL];
__device__ uint16_t g_Wk[(size_t)D_MODEL * D_MODEL];
__device__ uint16_t g_Wv[(size_t)D_MODEL * D_MODEL];
__device__ uint16_t g_Wo[(size_t)D_MODEL * D_MODEL];

__device__ __forceinline__ uint32_t f2h2(float a, float b) {
    __half2 h = __floats2half2_rn(a, b);
    return *reinterpret_cast<uint32_t*>(&h);
}

__device__ __forceinline__ void mma_f16(float c[4], const uint32_t a[4], const uint32_t b[2]) {
    asm volatile(
        "mma.sync.aligned.m16n8k16.row.col.f32.f16.f16.f32 "
        "{%0,%1,%2,%3},{%4,%5,%6,%7},{%8,%9},{%0,%1,%2,%3};"
        : "+f"(c[0]), "+f"(c[1]), "+f"(c[2]), "+f"(c[3])
        : "r"(a[0]), "r"(a[1]), "r"(a[2]), "r"(a[3]), "r"(b[0]), "r"(b[1]));
}

__device__ __forceinline__ void cp_async16(void* sptr, const void* gptr) {
    uint32_t s = (uint32_t)__cvta_generic_to_shared(sptr);
    asm volatile("cp.async.cg.shared.global [%0], [%1], 16;" :: "r"(s), "l"(gptr));
}
__device__ __forceinline__ void cp_commit() { asm volatile("cp.async.commit_group;"); }
template<int N> __device__ __forceinline__ void cp_wait() {
    asm volatile("cp.async.wait_group %0;" :: "n"(N));
}

// ---------------------------------------------------------------------------
// Activation prepass: fp32 -> half, 3 tensors (grid.z selects). 8 floats/thread.
// ---------------------------------------------------------------------------
__global__ void acvt_kernel(const float4* __restrict__ a0, uint4* __restrict__ o0,
                            const float4* __restrict__ a1, uint4* __restrict__ o1,
                            const float4* __restrict__ a2, uint4* __restrict__ o2,
                            int n8)
{
    const float4* in; uint4* out;
    switch (blockIdx.z) {
        case 0: in = a0; out = o0; break;
        case 1: in = a1; out = o1; break;
        default: in = a2; out = o2; break;
    }
    int i = blockIdx.x * blockDim.x + threadIdx.x;
    if (i < n8) {
        float4 u = in[2*i], v = in[2*i + 1];
        uint4 st;
        st.x = f2h2(u.x, u.y); st.y = f2h2(u.z, u.w);
        st.z = f2h2(v.x, v.y); st.w = f2h2(v.z, v.w);
        out[i] = st;
    }
}

// ---------------------------------------------------------------------------
// Weight prepass: transpose + half-round all 4 weight matrices.
// ---------------------------------------------------------------------------
__global__ void wtrans_kernel(const float* __restrict__ w0, uint16_t* __restrict__ o0,
                              const float* __restrict__ w1, uint16_t* __restrict__ o1,
                              const float* __restrict__ w2, uint16_t* __restrict__ o2,
                              const float* __restrict__ w3, uint16_t* __restrict__ o3)
{
    __shared__ float tile[32][33];
    const float* W; uint16_t* O;
    switch (blockIdx.z) {
        case 0: W = w0; O = o0; break;
        case 1: W = w1; O = o1; break;
        case 2: W = w2; O = o2; break;
        default: W = w3; O = o3; break;
    }
    int bx = blockIdx.x * 32;   // n block
    int by = blockIdx.y * 32;   // k block
    int tx = threadIdx.x, ty = threadIdx.y;
    #pragma unroll
    for (int i = 0; i < 4; i++)
        tile[ty + 8*i][tx] = W[(size_t)(by + ty + 8*i) * D_MODEL + bx + tx];
    __syncthreads();
    #pragma unroll
    for (int i = 0; i < 4; i++) {
        __half h = __float2half_rn(tile[tx][ty + 8*i]);
        O[(size_t)(bx + ty + 8*i) * D_MODEL + by + tx] = *reinterpret_cast<uint16_t*>(&h);
    }
}

// ===========================================================================
// fp16 tensor-core GEMM: C[M,N] = A[M,K] @ Wt^T + bias  (A, Wt both half)
// BM=BN=128, BK=32 halves, 256 threads (8 warps, 64x32 warp tiles),
// 4-stage cp.async pipeline with cp_wait<2>.
// REMAP=1: bias + half-round + head-split store; z==0 (Q) pre-scales by 0.125;
//          z==2 (V) stores TRANSPOSED.
// ===========================================================================
#define ALD 40                    // halves per smem row (32 + 8 pad); 80 B
#define STG (128 * ALD)           // halves per operand per stage
#define NSTG 4
#define GEMM_SMEM (2 * NSTG * STG * 2)   // 81920 B

template<int REMAP>
__global__ __launch_bounds__(256, 2)
void gemm_h(const uint16_t* __restrict__ A0, const uint16_t* __restrict__ W0,
            const float* __restrict__ b0p, void* __restrict__ C0,
            const uint16_t* __restrict__ A1, const uint16_t* __restrict__ W1,
            const float* __restrict__ b1p, void* __restrict__ C1,
            const uint16_t* __restrict__ A2, const uint16_t* __restrict__ W2,
            const float* __restrict__ b2p, void* __restrict__ C2)
{
    const int K = D_MODEL, N = D_MODEL;
    extern __shared__ uint16_t smh[];
    uint16_t* As = smh;               // [NSTG][128][ALD]
    uint16_t* Bs = smh + NSTG * STG;  // [NSTG][128][ALD]

    const uint16_t *Ah, *Wt; const float* bias; void* Cv;
    const int zsel = blockIdx.z;
    switch (zsel) {
        case 0:  Ah = A0; Wt = W0; bias = b0p; Cv = C0; break;
        case 1:  Ah = A1; Wt = W1; bias = b1p; Cv = C1; break;
        default: Ah = A2; Wt = W2; bias = b2p; Cv = C2; break;
    }

    const int t    = threadIdx.x;
    const int lane = t & 31;
    const int warp = t >> 5;
    const int g    = lane >> 2;
    const int tg   = lane & 3;
    const int wm   = (warp & 1) * 64;
    const int wn   = (warp >> 1) * 32;
    const int m0   = blockIdx.y * 128;
    const int n0   = blockIdx.x * 128;

    // cooperative load: 128 rows x 32 halves, 2 threads/row, 16 halves each
    const int lrow = t >> 1;
    const int lhlf = (t & 1) * 16;

    float acc[4][4][4] = {};

    const int NCHUNK = K / 32;   // 32

    // ---- Prologue: stages 0..2 ----
    #pragma unroll
    for (int st = 0; st < NSTG - 1; st++) {
        uint16_t* Ad = As + st * STG;
        uint16_t* Bd = Bs + st * STG;
        #pragma unroll
        for (int p = 0; p < 2; p++) {
            cp_async16(&Ad[lrow * ALD + lhlf + 8*p],
                       &Ah[(size_t)(m0 + lrow) * K + st * 32 + lhlf + 8*p]);
            cp_async16(&Bd[lrow * ALD + lhlf + 8*p],
                       &Wt[(size_t)(n0 + lrow) * K + st * 32 + lhlf + 8*p]);
        }
        cp_commit();
    }

    for (int c = 0; c < NCHUNK; c++) {
        if (c + 3 <= NCHUNK)      cp_wait<2>();
        else if (c + 2 == NCHUNK) cp_wait<1>();
        else                      cp_wait<0>();
        __syncthreads();
        const int s = c % NSTG;
        if (c + 3 < NCHUNK) {
            const int sn = (c + 3) % NSTG;
            const int kn = (c + 3) * 32;
            uint16_t* Ad = As + sn * STG;
            uint16_t* Bd = Bs + sn * STG;
            #pragma unroll
            for (int p = 0; p < 2; p++) {
                cp_async16(&Ad[lrow * ALD + lhlf + 8*p],
                           &Ah[(size_t)(m0 + lrow) * K + kn + lhlf + 8*p]);
                cp_async16(&Bd[lrow * ALD + lhlf + 8*p],
                           &Wt[(size_t)(n0 + lrow) * K + kn + lhlf + 8*p]);
            }
            cp_commit();
        }
        const uint16_t* Ac = As + s * STG;
        const uint16_t* Bc = Bs + s * STG;
        #pragma unroll
        for (int ks = 0; ks < 2; ks++) {
            const int kk = ks * 16 + 2 * tg;
            uint32_t a[4][4], b[4][2];
            #pragma unroll
            for (int mt = 0; mt < 4; mt++) {
                int m = wm + mt * 16 + g;
                a[mt][0] = *(const uint32_t*)&Ac[m * ALD + kk];
                a[mt][1] = *(const uint32_t*)&Ac[(m + 8) * ALD + kk];
                a[mt][2] = *(const uint32_t*)&Ac[m * ALD + kk + 8];
                a[mt][3] = *(const uint32_t*)&Ac[(m + 8) * ALD + kk + 8];
            }
            #pragma unroll
            for (int nt = 0; nt < 4; nt++) {
                int n = wn + nt * 8 + g;
                b[nt][0] = *(const uint32_t*)&Bc[n * ALD + kk];
                b[nt][1] = *(const uint32_t*)&Bc[n * ALD + kk + 8];
            }
            #pragma unroll
            for (int mt = 0; mt < 4; mt++)
                #pragma unroll
                for (int nt = 0; nt < 4; nt++)
                    mma_f16(acc[mt][nt], a[mt], b[nt]);
        }
    }

    // ---- Epilogue ----
    #pragma unroll
    for (int mt = 0; mt < 4; mt++) {
        #pragma unroll
        for (int nt = 0; nt < 4; nt++) {
            int n  = n0 + wn + nt * 8 + 2 * tg;
            float b0v = bias[n], b1v = bias[n + 1];
            #pragma unroll
            for (int half = 0; half < 2; half++) {
                int m = m0 + wm + mt * 16 + g + half * 8;
                float vx = acc[mt][nt][half*2 + 0] + b0v;
                float vy = acc[mt][nt][half*2 + 1] + b1v;
                if (REMAP) {
                    uint16_t* Ch = (uint16_t*)Cv;
                    int bb = m >> 11, srow = m & 2047;
                    int hh = n >> 6, dd = n & 63;
                    if (zsel == 0) {
                        // Q: fold attention scale (exact power of two)
                        vx *= 0.125f; vy *= 0.125f;
                    }
                    if (zsel == 2) {
                        // V: store transposed [B,H,hd,S]
                        __half h0 = __float2half_rn(vx), h1 = __float2half_rn(vy);
                        size_t base = ((size_t)(bb * NHEADS + hh)) * HDIM;
                        Ch[(base + dd)     * SEQ + srow] = *reinterpret_cast<uint16_t*>(&h0);
                        Ch[(base + dd + 1) * SEQ + srow] = *reinterpret_cast<uint16_t*>(&h1);
                    } else {
                        *(uint32_t*)&Ch[(((size_t)(bb * NHEADS + hh)) * SEQ + srow) * HDIM + dd]
                            = f2h2(vx, vy);
                    }
                } else {
                    float* Cf = (float*)Cv;
                    *(float2*)&Cf[(size_t)m * N + n] = make_float2(vx, vy);
                }
            }
        }
    }
}

// ---------------------------------------------------------------------------
// Causal flash attention, fp16 mma, register-resident softmax.
// Q pre-scaled by 0.125. Longest-first CTA order (qt descending in blockIdx.x).
// Q/K half [B,H,S,hd]; V half PRE-TRANSPOSED [B,H,hd,S]; ctx half [B,S,D].
// CTA = 256 threads (8 warps) on 128q x 64k tile; warp = 16q x 64k.
// ---------------------------------------------------------------------------
#define FLD 72   // halves per smem row (64 + 8 pad); 144 B
#define FLASH_SMEM ((128*FLD + 128*FLD + 2*64*FLD + 2*64*FLD) * 2)   // 73728 B

__global__ __launch_bounds__(256, 2)
void flash_h(const uint16_t* __restrict__ Q, const uint16_t* __restrict__ K,
             const uint16_t* __restrict__ V, uint16_t* __restrict__ ctx)
{
    extern __shared__ uint16_t smh[];
    uint16_t* Qs = smh;                    // [128][FLD]
    uint16_t* Ps = smh + 128 * FLD;        // [128][FLD]
    uint16_t* Ks = smh + 2 * 128 * FLD;    // [2][64][FLD]   Ks[k][d]
    uint16_t* Vs = Ks + 2 * 64 * FLD;      // [2][64][FLD]   Vs[d][k]

    const int t    = threadIdx.x;
    const int lane = t & 31;
    const int warp = t >> 5;
    const int g    = lane >> 2;
    const int tg   = lane & 3;
    const int wq   = warp * 16;
    const int qt   = (int)gridDim.x - 1 - (int)blockIdx.x;   // longest-first
    const int bh   = blockIdx.y;
    const int q0   = qt * 128;
    const int kt_max = 2 * qt + 1;

    // cooperative load indices
    const int qr = t >> 1, qc = (t & 1) * 32;        // Q: 128 rows, 2 thr/row
    const int kr = t >> 2, kc = (t & 3) * 16;        // K/V: 64 rows, 4 thr/row

    {
        const uint16_t* Qb = Q + ((size_t)bh * SEQ + q0) * HDIM;
        #pragma unroll
        for (int p = 0; p < 4; p++)
            cp_async16(&Qs[qr * FLD + qc + 8*p], &Qb[qr * HDIM + qc + 8*p]);
    }
    {
        const uint16_t* Kb = K + (size_t)bh * SEQ * HDIM;
        const uint16_t* Vb = V + (size_t)bh * HDIM * SEQ;
        #pragma unroll
        for (int p = 0; p < 2; p++) {
            cp_async16(&Ks[kr * FLD + kc + 8*p], &Kb[kr * HDIM + kc + 8*p]);
            cp_async16(&Vs[kr * FLD + kc + 8*p], &Vb[(size_t)kr * SEQ + kc + 8*p]);
        }
    }
    cp_commit();

    float m0r = -INFINITY, m1r = -INFINITY;
    float l0r = 0.f, l1r = 0.f;
    float o[8][4] = {};

    const int row0 = q0 + wq + g;
    const int row1 = row0 + 8;

    for (int kt = 0; kt <= kt_max; kt++) {
        cp_wait<0>();
        __syncthreads();
        const int s = kt & 1;
        if (kt < kt_max) {
            const int kn = (kt + 1) * 64;
            const uint16_t* Kb = K + ((size_t)bh * SEQ + kn) * HDIM;
            const uint16_t* Vb = V + (size_t)bh * HDIM * SEQ + kn;
            uint16_t* Kn = Ks + (s ^ 1) * 64 * FLD;
            uint16_t* Vn = Vs + (s ^ 1) * 64 * FLD;
            #pragma unroll
            for (int p = 0; p < 2; p++) {
                cp_async16(&Kn[kr * FLD + kc + 8*p], &Kb[kr * HDIM + kc + 8*p]);
                cp_async16(&Vn[kr * FLD + kc + 8*p], &Vb[(size_t)kr * SEQ + kc + 8*p]);
            }
            cp_commit();
        }
        const uint16_t* Kc = Ks + s * 64 * FLD;
        const uint16_t* Vc = Vs + s * 64 * FLD;
        const int k0 = kt * 64;

        // ---- S = (Q*0.125) K^T  (scale pre-folded into Q) ----
        float sc[8][4] = {};
        #pragma unroll
        for (int ks = 0; ks < 4; ks++) {
            const int kk = ks * 16 + 2 * tg;
            uint32_t a[4], b[8][2];
            a[0] = *(const uint32_t*)&Qs[(wq + g) * FLD + kk];
            a[1] = *(const uint32_t*)&Qs[(wq + g + 8) * FLD + kk];
            a[2] = *(const uint32_t*)&Qs[(wq + g) * FLD + kk + 8];
            a[3] = *(const uint32_t*)&Qs[(wq + g + 8) * FLD + kk + 8];
            #pragma unroll
            for (int nt = 0; nt < 8; nt++) {
                int n = nt * 8 + g;
                b[nt][0] = *(const uint32_t*)&Kc[n * FLD + kk];
                b[nt][1] = *(const uint32_t*)&Kc[n * FLD + kk + 8];
            }
            #pragma unroll
            for (int nt = 0; nt < 8; nt++)
                mma_f16(sc[nt], a, b[nt]);
        }

        // ---- causal mask (select only; no scale multiply) ----
        if (k0 + 63 > row0) {
            #pragma unroll
            for (int nt = 0; nt < 8; nt++) {
                int c = k0 + nt * 8 + 2 * tg;
                if (c     > row0) sc[nt][0] = -INFINITY;
                if (c + 1 > row0) sc[nt][1] = -INFINITY;
                if (c     > row1) sc[nt][2] = -INFINITY;
                if (c + 1 > row1) sc[nt][3] = -INFINITY;
            }
        }

        // ---- row max (registers + quad shuffle) ----
        float mx0 = -INFINITY, mx1 = -INFINITY;
        #pragma unroll
        for (int nt = 0; nt < 8; nt++) {
            mx0 = fmaxf(mx0, fmaxf(sc[nt][0], sc[nt][1]));
            mx1 = fmaxf(mx1, fmaxf(sc[nt][2], sc[nt][3]));
        }
        mx0 = fmaxf(mx0, __shfl_xor_sync(0xffffffff, mx0, 1));
        mx0 = fmaxf(mx0, __shfl_xor_sync(0xffffffff, mx0, 2));
        mx1 = fmaxf(mx1, __shfl_xor_sync(0xffffffff, mx1, 1));
        mx1 = fmaxf(mx1, __shfl_xor_sync(0xffffffff, mx1, 2));

        float mn0 = fmaxf(m0r, mx0), mn1 = fmaxf(m1r, mx1);
        float al0 = __expf(m0r - mn0), al1 = __expf(m1r - mn1);
        m0r = mn0; m1r = mn1;

        // ---- exp (half-rounded), row sums over rounded values, write P ----
        float s0 = 0.f, s1 = 0.f;
        #pragma unroll
        for (int nt = 0; nt < 8; nt++) {
            __half2 hp0 = __floats2half2_rn(__expf(sc[nt][0] - mn0), __expf(sc[nt][1] - mn0));
            __half2 hp1 = __floats2half2_rn(__expf(sc[nt][2] - mn1), __expf(sc[nt][3] - mn1));
            float2 r0 = __half22float2(hp0);
            float2 r1 = __half22float2(hp1);
            s0 += r0.x + r0.y;
            s1 += r1.x + r1.y;
            int c = nt * 8 + 2 * tg;
            *(uint32_t*)&Ps[(wq + g) * FLD + c]     = *reinterpret_cast<uint32_t*>(&hp0);
            *(uint32_t*)&Ps[(wq + g + 8) * FLD + c] = *reinterpret_cast<uint32_t*>(&hp1);
        }
        s0 += __shfl_xor_sync(0xffffffff, s0, 1);
        s0 += __shfl_xor_sync(0xffffffff, s0, 2);
        s1 += __shfl_xor_sync(0xffffffff, s1, 1);
        s1 += __shfl_xor_sync(0xffffffff, s1, 2);
        l0r = l0r * al0 + s0;
        l1r = l1r * al1 + s1;

        // ---- rescale O only when some lane's max moved ----
        bool no_rescale = (al0 == 1.f) && (al1 == 1.f);
        if (!__all_sync(0xffffffff, no_rescale)) {
            #pragma unroll
            for (int nt = 0; nt < 8; nt++) {
                o[nt][0] *= al0; o[nt][1] *= al0;
                o[nt][2] *= al1; o[nt][3] *= al1;
            }
        }
        __syncwarp();   // P tile is warp-private

        // ---- O += P V ----
        #pragma unroll
        for (int ks = 0; ks < 4; ks++) {
            const int kk = ks * 16 + 2 * tg;
            uint32_t a[4], b[8][2];
            a[0] = *(const uint32_t*)&Ps[(wq + g) * FLD + kk];
            a[1] = *(const uint32_t*)&Ps[(wq + g + 8) * FLD + kk];
            a[2] = *(const uint32_t*)&Ps[(wq + g) * FLD + kk + 8];
            a[3] = *(const uint32_t*)&Ps[(wq + g + 8) * FLD + kk + 8];
            #pragma unroll
            for (int nt = 0; nt < 8; nt++) {
                int d = nt * 8 + g;
                b[nt][0] = *(const uint32_t*)&Vc[d * FLD + kk];
                b[nt][1] = *(const uint32_t*)&Vc[d * FLD + kk + 8];
            }
            #pragma unroll
            for (int nt = 0; nt < 8; nt++)
                mma_f16(o[nt], a, b[nt]);
        }
    }

    // Epilogue: normalize, half-round, write ctx [B,S,D] half
    const int bb = bh >> 4;
    const int hh = bh & 15;
    const float il0 = 1.f / l0r, il1 = 1.f / l1r;
    #pragma unroll
    for (int nt = 0; nt < 8; nt++) {
        int d = nt * 8 + 2 * tg;
        *(uint32_t*)&ctx[((size_t)bb * SEQ + row0) * D_MODEL + hh * HDIM + d]
            = f2h2(o[nt][0] * il0, o[nt][1] * il0);
        *(uint32_t*)&ctx[((size_t)bb * SEQ + row1) * D_MODEL + hh * HDIM + d]
            = f2h2(o[nt][2] * il1, o[nt][3] * il1);
    }
}

// ---------------------------------------------------------------------------
extern "C" void kernel_launch(void* const* d_in, const int* in_sizes, int n_in,
                              void* d_out, int out_size)
{
    const float* in_q = (const float*)d_in[0];
    const float* in_k = (const float*)d_in[1];
    const float* in_v = (const float*)d_in[2];
    const float* Wq   = (const float*)d_in[3];
    const float* bq   = (const float*)d_in[4];
    const float* Wk   = (const float*)d_in[5];
    const float* bk   = (const float*)d_in[6];
    const float* Wv   = (const float*)d_in[7];
    const float* bv   = (const float*)d_in[8];
    const float* Wo   = (const float*)d_in[9];
    const float* bo   = (const float*)d_in[10];
    float* out = (float*)d_out;

    uint16_t *gq, *gk, *gv, *gc, *aq, *ak, *av, *wq, *wk, *wv, *wo;
    cudaGetSymbolAddress((void**)&gq, g_Q);
    cudaGetSymbolAddress((void**)&gk, g_K);
    cudaGetSymbolAddress((void**)&gv, g_V);
    cudaGetSymbolAddress((void**)&gc, g_C);
    cudaGetSymbolAddress((void**)&aq, g_Aq);
    cudaGetSymbolAddress((void**)&ak, g_Ak);
    cudaGetSymbolAddress((void**)&av, g_Av);
    cudaGetSymbolAddress((void**)&wq, g_Wq);
    cudaGetSymbolAddress((void**)&wk, g_Wk);
    cudaGetSymbolAddress((void**)&wv, g_Wv);
    cudaGetSymbolAddress((void**)&wo, g_Wo);

    static int attr_set = 0;
    if (!attr_set) {
        cudaFuncSetAttribute(gemm_h<1>, cudaFuncAttributeMaxDynamicSharedMemorySize, GEMM_SMEM);
        cudaFuncSetAttribute(gemm_h<0>, cudaFuncAttributeMaxDynamicSharedMemorySize, GEMM_SMEM);
        cudaFuncSetAttribute(flash_h,   cudaFuncAttributeMaxDynamicSharedMemorySize, FLASH_SMEM);
        attr_set = 1;
    }

    // Prepass: weights (transpose+round) and activations (round), 2 launches
    dim3 wt_grid(32, 32, 4);
    wtrans_kernel<<<wt_grid, dim3(32, 8)>>>(Wq, wq, Wk, wk, Wv, wv, Wo, wo);
    const int n8 = MROWS * D_MODEL / 8;   // 1M
    dim3 ac_grid((n8 + 255)/256, 1, 3);
    acvt_kernel<<<ac_grid, 256>>>((const float4*)in_q, (uint4*)aq,
                                  (const float4*)in_k, (uint4*)ak,
                                  (const float4*)in_v, (uint4*)av, n8);

    // Fused QKV projections, one launch (z selects problem)
    dim3 qkv_grid(D_MODEL / 128, MROWS / 128, 3);   // (8, 64, 3)
    gemm_h<1><<<qkv_grid, 256, GEMM_SMEM>>>(aq, wq, bq, gq,
                                            ak, wk, bk, gk,
                                            av, wv, bv, gv);

    dim3 attn_grid(SEQ / 128, BATCH * NHEADS);      // (16, 64)
    flash_h<<<attn_grid, 256, FLASH_SMEM>>>(gq, gk, gv, gc);

    // O-projection: A = half ctx, output fp32 + bias
    dim3 o_grid(D_MODEL / 128, MROWS / 128, 1);     // (8, 64)
    gemm_h<0><<<o_grid, 256, GEMM_SMEM>>>(gc, wo, bo, out,
                                          gc, wo, bo, out,
                                          gc, wo, bo, out);
}

// round 15
// speedup vs baseline: 1.1392x; 1.0277x over previous
#include <cuda_runtime.h>
#include <cuda_fp16.h>
#include <math.h>
#include <stdint.h>

#define D_MODEL 1024
#define NHEADS  16
#define HDIM    64
#define BATCH   4
#define SEQ     2048
#define MROWS   (BATCH*SEQ)   // 8192

// Scratch (device globals — no allocations allowed). Halves stored as uint16_t.
__device__ uint16_t g_Q[(size_t)MROWS * D_MODEL];   // [B,H,S,hd] half, PRE-SCALED by 0.125*log2e
__device__ uint16_t g_K[(size_t)MROWS * D_MODEL];   // [B,H,S,hd] half
__device__ uint16_t g_V[(size_t)MROWS * D_MODEL];   // [B,H,hd,S] half (pre-transposed!)
__device__ uint16_t g_C[(size_t)MROWS * D_MODEL];   // [B,S,D]    half
// half activations (pre-rounded)
__device__ uint16_t g_Aq[(size_t)MROWS * D_MODEL];
__device__ uint16_t g_Ak[(size_t)MROWS * D_MODEL];
__device__ uint16_t g_Av[(size_t)MROWS * D_MODEL];
// half TRANSPOSED weights: Wt[n][k] = half(W[k][n])
__device__ uint16_t g_Wq[(size_t)D_MODEL * D_MODEL];
__device__ uint16_t g_Wk[(size_t)D_MODEL * D_MODEL];
__device__ uint16_t g_Wv[(size_t)D_MODEL * D_MODEL];
__device__ uint16_t g_Wo[(size_t)D_MODEL * D_MODEL];

// 0.125 (1/sqrt(64)) * log2(e): Q is stored in the log2-softmax domain.
#define QSCALE (0.125f * 1.4426950408889634f)

__device__ __forceinline__ uint32_t f2h2(float a, float b) {
    __half2 h = __floats2half2_rn(a, b);
    return *reinterpret_cast<uint32_t*>(&h);
}

__device__ __forceinline__ void mma_f16(float c[4], const uint32_t a[4], const uint32_t b[2]) {
    asm volatile(
        "mma.sync.aligned.m16n8k16.row.col.f32.f16.f16.f32 "
        "{%0,%1,%2,%3},{%4,%5,%6,%7},{%8,%9},{%0,%1,%2,%3};"
        : "+f"(c[0]), "+f"(c[1]), "+f"(c[2]), "+f"(c[3])
        : "r"(a[0]), "r"(a[1]), "r"(a[2]), "r"(a[3]), "r"(b[0]), "r"(b[1]));
}

__device__ __forceinline__ void cp_async16(void* sptr, const void* gptr) {
    uint32_t s = (uint32_t)__cvta_generic_to_shared(sptr);
    asm volatile("cp.async.cg.shared.global [%0], [%1], 16;" :: "r"(s), "l"(gptr));
}
__device__ __forceinline__ void cp_commit() { asm volatile("cp.async.commit_group;"); }
template<int N> __device__ __forceinline__ void cp_wait() {
    asm volatile("cp.async.wait_group %0;" :: "n"(N));
}

// ---------------------------------------------------------------------------
// Activation prepass: fp32 -> half, 3 tensors (grid.z selects). 8 floats/thread.
// ---------------------------------------------------------------------------
__global__ void acvt_kernel(const float4* __restrict__ a0, uint4* __restrict__ o0,
                            const float4* __restrict__ a1, uint4* __restrict__ o1,
                            const float4* __restrict__ a2, uint4* __restrict__ o2,
                            int n8)
{
    const float4* in; uint4* out;
    switch (blockIdx.z) {
        case 0: in = a0; out = o0; break;
        case 1: in = a1; out = o1; break;
        default: in = a2; out = o2; break;
    }
    int i = blockIdx.x * blockDim.x + threadIdx.x;
    if (i < n8) {
        float4 u = in[2*i], v = in[2*i + 1];
        uint4 st;
        st.x = f2h2(u.x, u.y); st.y = f2h2(u.z, u.w);
        st.z = f2h2(v.x, v.y); st.w = f2h2(v.z, v.w);
        out[i] = st;
    }
}

// ---------------------------------------------------------------------------
// Weight prepass: transpose + half-round all 4 weight matrices.
// ---------------------------------------------------------------------------
__global__ void wtrans_kernel(const float* __restrict__ w0, uint16_t* __restrict__ o0,
                              const float* __restrict__ w1, uint16_t* __restrict__ o1,
                              const float* __restrict__ w2, uint16_t* __restrict__ o2,
                              const float* __restrict__ w3, uint16_t* __restrict__ o3)
{
    __shared__ float tile[32][33];
    const float* W; uint16_t* O;
    switch (blockIdx.z) {
        case 0: W = w0; O = o0; break;
        case 1: W = w1; O = o1; break;
        case 2: W = w2; O = o2; break;
        default: W = w3; O = o3; break;
    }
    int bx = blockIdx.x * 32;   // n block
    int by = blockIdx.y * 32;   // k block
    int tx = threadIdx.x, ty = threadIdx.y;
    #pragma unroll
    for (int i = 0; i < 4; i++)
        tile[ty + 8*i][tx] = W[(size_t)(by + ty + 8*i) * D_MODEL + bx + tx];
    __syncthreads();
    #pragma unroll
    for (int i = 0; i < 4; i++) {
        __half h = __float2half_rn(tile[tx][ty + 8*i]);
        O[(size_t)(bx + ty + 8*i) * D_MODEL + by + tx] = *reinterpret_cast<uint16_t*>(&h);
    }
}

// ===========================================================================
// fp16 tensor-core GEMM: C[M,N] = A[M,K] @ Wt^T + bias  (A, Wt both half)
// BM=BN=128, BK=32 halves, 256 threads (8 warps, 64x32 warp tiles),
// 4-stage cp.async pipeline with cp_wait<2>.
// REMAP=1: bias + half-round + head-split store; z==0 (Q) pre-scales by QSCALE;
//          z==2 (V) stores TRANSPOSED.
// ===========================================================================
#define ALD 40                    // halves per smem row (32 + 8 pad); 80 B
#define STG (128 * ALD)           // halves per operand per stage
#define NSTG 4
#define GEMM_SMEM (2 * NSTG * STG * 2)   // 81920 B

template<int REMAP>
__global__ __launch_bounds__(256, 2)
void gemm_h(const uint16_t* __restrict__ A0, const uint16_t* __restrict__ W0,
            const float* __restrict__ b0p, void* __restrict__ C0,
            const uint16_t* __restrict__ A1, const uint16_t* __restrict__ W1,
            const float* __restrict__ b1p, void* __restrict__ C1,
            const uint16_t* __restrict__ A2, const uint16_t* __restrict__ W2,
            const float* __restrict__ b2p, void* __restrict__ C2)
{
    const int K = D_MODEL, N = D_MODEL;
    extern __shared__ uint16_t smh[];
    uint16_t* As = smh;               // [NSTG][128][ALD]
    uint16_t* Bs = smh + NSTG * STG;  // [NSTG][128][ALD]

    const uint16_t *Ah, *Wt; const float* bias; void* Cv;
    const int zsel = blockIdx.z;
    switch (zsel) {
        case 0:  Ah = A0; Wt = W0; bias = b0p; Cv = C0; break;
        case 1:  Ah = A1; Wt = W1; bias = b1p; Cv = C1; break;
        default: Ah = A2; Wt = W2; bias = b2p; Cv = C2; break;
    }

    const int t    = threadIdx.x;
    const int lane = t & 31;
    const int warp = t >> 5;
    const int g    = lane >> 2;
    const int tg   = lane & 3;
    const int wm   = (warp & 1) * 64;
    const int wn   = (warp >> 1) * 32;
    const int m0   = blockIdx.y * 128;
    const int n0   = blockIdx.x * 128;

    // cooperative load: 128 rows x 32 halves, 2 threads/row, 16 halves each
    const int lrow = t >> 1;
    const int lhlf = (t & 1) * 16;

    float acc[4][4][4] = {};

    const int NCHUNK = K / 32;   // 32

    // ---- Prologue: stages 0..2 ----
    #pragma unroll
    for (int st = 0; st < NSTG - 1; st++) {
        uint16_t* Ad = As + st * STG;
        uint16_t* Bd = Bs + st * STG;
        #pragma unroll
        for (int p = 0; p < 2; p++) {
            cp_async16(&Ad[lrow * ALD + lhlf + 8*p],
                       &Ah[(size_t)(m0 + lrow) * K + st * 32 + lhlf + 8*p]);
            cp_async16(&Bd[lrow * ALD + lhlf + 8*p],
                       &Wt[(size_t)(n0 + lrow) * K + st * 32 + lhlf + 8*p]);
        }
        cp_commit();
    }

    for (int c = 0; c < NCHUNK; c++) {
        if (c + 3 <= NCHUNK)      cp_wait<2>();
        else if (c + 2 == NCHUNK) cp_wait<1>();
        else                      cp_wait<0>();
        __syncthreads();
        const int s = c % NSTG;
        if (c + 3 < NCHUNK) {
            const int sn = (c + 3) % NSTG;
            const int kn = (c + 3) * 32;
            uint16_t* Ad = As + sn * STG;
            uint16_t* Bd = Bs + sn * STG;
            #pragma unroll
            for (int p = 0; p < 2; p++) {
                cp_async16(&Ad[lrow * ALD + lhlf + 8*p],
                           &Ah[(size_t)(m0 + lrow) * K + kn + lhlf + 8*p]);
                cp_async16(&Bd[lrow * ALD + lhlf + 8*p],
                           &Wt[(size_t)(n0 + lrow) * K + kn + lhlf + 8*p]);
            }
            cp_commit();
        }
        const uint16_t* Ac = As + s * STG;
        const uint16_t* Bc = Bs + s * STG;
        #pragma unroll
        for (int ks = 0; ks < 2; ks++) {
            const int kk = ks * 16 + 2 * tg;
            uint32_t a[4][4], b[4][2];
            #pragma unroll
            for (int mt = 0; mt < 4; mt++) {
                int m = wm + mt * 16 + g;
                a[mt][0] = *(const uint32_t*)&Ac[m * ALD + kk];
                a[mt][1] = *(const uint32_t*)&Ac[(m + 8) * ALD + kk];
                a[mt][2] = *(const uint32_t*)&Ac[m * ALD + kk + 8];
                a[mt][3] = *(const uint32_t*)&Ac[(m + 8) * ALD + kk + 8];
            }
            #pragma unroll
            for (int nt = 0; nt < 4; nt++) {
                int n = wn + nt * 8 + g;
                b[nt][0] = *(const uint32_t*)&Bc[n * ALD + kk];
                b[nt][1] = *(const uint32_t*)&Bc[n * ALD + kk + 8];
            }
            #pragma unroll
            for (int mt = 0; mt < 4; mt++)
                #pragma unroll
                for (int nt = 0; nt < 4; nt++)
                    mma_f16(acc[mt][nt], a[mt], b[nt]);
        }
    }

    // ---- Epilogue ----
    #pragma unroll
    for (int mt = 0; mt < 4; mt++) {
        #pragma unroll
        for (int nt = 0; nt < 4; nt++) {
            int n  = n0 + wn + nt * 8 + 2 * tg;
            float b0v = bias[n], b1v = bias[n + 1];
            #pragma unroll
            for (int half = 0; half < 2; half++) {
                int m = m0 + wm + mt * 16 + g + half * 8;
                float vx = acc[mt][nt][half*2 + 0] + b0v;
                float vy = acc[mt][nt][half*2 + 1] + b1v;
                if (REMAP) {
                    uint16_t* Ch = (uint16_t*)Cv;
                    int bb = m >> 11, srow = m & 2047;
                    int hh = n >> 6, dd = n & 63;
                    if (zsel == 0) {
                        // Q: fold attention scale * log2(e) (exp2 softmax domain)
                        vx *= QSCALE; vy *= QSCALE;
                    }
                    if (zsel == 2) {
                        // V: store transposed [B,H,hd,S]
                        __half h0 = __float2half_rn(vx), h1 = __float2half_rn(vy);
                        size_t base = ((size_t)(bb * NHEADS + hh)) * HDIM;
                        Ch[(base + dd)     * SEQ + srow] = *reinterpret_cast<uint16_t*>(&h0);
                        Ch[(base + dd + 1) * SEQ + srow] = *reinterpret_cast<uint16_t*>(&h1);
                    } else {
                        *(uint32_t*)&Ch[(((size_t)(bb * NHEADS + hh)) * SEQ + srow) * HDIM + dd]
                            = f2h2(vx, vy);
                    }
                } else {
                    float* Cf = (float*)Cv;
                    *(float2*)&Cf[(size_t)m * N + n] = make_float2(vx, vy);
                }
            }
        }
    }
}

// ---------------------------------------------------------------------------
// Causal flash attention, fp16 mma, register-resident softmax AND P.
// The S-mma C-fragment layout (rows g,g+8 x cols 2tg,2tg+1 per 8-col block)
// equals the PV-mma A-fragment layout: P never touches smem.
// Q pre-scaled by 0.125*log2e; softmax runs in exp2 domain.
// Q/K half [B,H,S,hd]; V half PRE-TRANSPOSED [B,H,hd,S]; ctx half [B,S,D].
// CTA = 256 threads (8 warps) on 128q x 64k tile; warp = 16q x 64k.
// ---------------------------------------------------------------------------
#define FLD 72   // halves per smem row (64 + 8 pad); 144 B
#define FLASH_SMEM ((128*FLD + 2*64*FLD + 2*64*FLD) * 2)   // 55296 B

__global__ __launch_bounds__(256, 2)
void flash_h(const uint16_t* __restrict__ Q, const uint16_t* __restrict__ K,
             const uint16_t* __restrict__ V, uint16_t* __restrict__ ctx)
{
    extern __shared__ uint16_t smh[];
    uint16_t* Qs = smh;                    // [128][FLD]
    uint16_t* Ks = smh + 128 * FLD;        // [2][64][FLD]   Ks[k][d]
    uint16_t* Vs = Ks + 2 * 64 * FLD;      // [2][64][FLD]   Vs[d][k]

    const int t    = threadIdx.x;
    const int lane = t & 31;
    const int warp = t >> 5;
    const int g    = lane >> 2;
    const int tg   = lane & 3;
    const int wq   = warp * 16;
    const int qt   = (int)gridDim.x - 1 - (int)blockIdx.x;   // longest-first
    const int bh   = blockIdx.y;
    const int q0   = qt * 128;
    const int kt_max = 2 * qt + 1;

    // cooperative load indices
    const int qr = t >> 1, qc = (t & 1) * 32;        // Q: 128 rows, 2 thr/row
    const int kr = t >> 2, kc = (t & 3) * 16;        // K/V: 64 rows, 4 thr/row

    {
        const uint16_t* Qb = Q + ((size_t)bh * SEQ + q0) * HDIM;
        #pragma unroll
        for (int p = 0; p < 4; p++)
            cp_async16(&Qs[qr * FLD + qc + 8*p], &Qb[qr * HDIM + qc + 8*p]);
    }
    {
        const uint16_t* Kb = K + (size_t)bh * SEQ * HDIM;
        const uint16_t* Vb = V + (size_t)bh * HDIM * SEQ;
        #pragma unroll
        for (int p = 0; p < 2; p++) {
            cp_async16(&Ks[kr * FLD + kc + 8*p], &Kb[kr * HDIM + kc + 8*p]);
            cp_async16(&Vs[kr * FLD + kc + 8*p], &Vb[(size_t)kr * SEQ + kc + 8*p]);
        }
    }
    cp_commit();

    float m0r = -INFINITY, m1r = -INFINITY;
    float l0r = 0.f, l1r = 0.f;
    float o[8][4] = {};

    const int row0 = q0 + wq + g;
    const int row1 = row0 + 8;

    for (int kt = 0; kt <= kt_max; kt++) {
        cp_wait<0>();
        __syncthreads();
        const int s = kt & 1;
        if (kt < kt_max) {
            const int kn = (kt + 1) * 64;
            const uint16_t* Kb = K + ((size_t)bh * SEQ + kn) * HDIM;
            const uint16_t* Vb = V + (size_t)bh * HDIM * SEQ + kn;
            uint16_t* Kn = Ks + (s ^ 1) * 64 * FLD;
            uint16_t* Vn = Vs + (s ^ 1) * 64 * FLD;
            #pragma unroll
            for (int p = 0; p < 2; p++) {
                cp_async16(&Kn[kr * FLD + kc + 8*p], &Kb[kr * HDIM + kc + 8*p]);
                cp_async16(&Vn[kr * FLD + kc + 8*p], &Vb[(size_t)kr * SEQ + kc + 8*p]);
            }
            cp_commit();
        }
        const uint16_t* Kc = Ks + s * 64 * FLD;
        const uint16_t* Vc = Vs + s * 64 * FLD;
        const int k0 = kt * 64;

        // ---- S = (Q*QSCALE) K^T  (log2-domain scores) ----
        float sc[8][4] = {};
        #pragma unroll
        for (int ks = 0; ks < 4; ks++) {
            const int kk = ks * 16 + 2 * tg;
            uint32_t a[4], b[8][2];
            a[0] = *(const uint32_t*)&Qs[(wq + g) * FLD + kk];
            a[1] = *(const uint32_t*)&Qs[(wq + g + 8) * FLD + kk];
            a[2] = *(const uint32_t*)&Qs[(wq + g) * FLD + kk + 8];
            a[3] = *(const uint32_t*)&Qs[(wq + g + 8) * FLD + kk + 8];
            #pragma unroll
            for (int nt = 0; nt < 8; nt++) {
                int n = nt * 8 + g;
                b[nt][0] = *(const uint32_t*)&Kc[n * FLD + kk];
                b[nt][1] = *(const uint32_t*)&Kc[n * FLD + kk + 8];
            }
            #pragma unroll
            for (int nt = 0; nt < 8; nt++)
                mma_f16(sc[nt], a, b[nt]);
        }

        // ---- causal mask (select only) ----
        if (k0 + 63 > row0) {
            #pragma unroll
            for (int nt = 0; nt < 8; nt++) {
                int c = k0 + nt * 8 + 2 * tg;
                if (c     > row0) sc[nt][0] = -INFINITY;
                if (c + 1 > row0) sc[nt][1] = -INFINITY;
                if (c     > row1) sc[nt][2] = -INFINITY;
                if (c + 1 > row1) sc[nt][3] = -INFINITY;
            }
        }

        // ---- row max (registers + quad shuffle) ----
        float mx0 = -INFINITY, mx1 = -INFINITY;
        #pragma unroll
        for (int nt = 0; nt < 8; nt++) {
            mx0 = fmaxf(mx0, fmaxf(sc[nt][0], sc[nt][1]));
            mx1 = fmaxf(mx1, fmaxf(sc[nt][2], sc[nt][3]));
        }
        mx0 = fmaxf(mx0, __shfl_xor_sync(0xffffffff, mx0, 1));
        mx0 = fmaxf(mx0, __shfl_xor_sync(0xffffffff, mx0, 2));
        mx1 = fmaxf(mx1, __shfl_xor_sync(0xffffffff, mx1, 1));
        mx1 = fmaxf(mx1, __shfl_xor_sync(0xffffffff, mx1, 2));

        float mn0 = fmaxf(m0r, mx0), mn1 = fmaxf(m1r, mx1);
        float al0 = exp2f(m0r - mn0), al1 = exp2f(m1r - mn1);
        m0r = mn0; m1r = mn1;

        // ---- exp2 (half-rounded), row sums, P stays in REGISTERS ----
        uint32_t p[8][2];
        float s0 = 0.f, s1 = 0.f;
        #pragma unroll
        for (int nt = 0; nt < 8; nt++) {
            __half2 hp0 = __floats2half2_rn(exp2f(sc[nt][0] - mn0), exp2f(sc[nt][1] - mn0));
            __half2 hp1 = __floats2half2_rn(exp2f(sc[nt][2] - mn1), exp2f(sc[nt][3] - mn1));
            float2 r0 = __half22float2(hp0);
            float2 r1 = __half22float2(hp1);
            s0 += r0.x + r0.y;
            s1 += r1.x + r1.y;
            p[nt][0] = *reinterpret_cast<uint32_t*>(&hp0);
            p[nt][1] = *reinterpret_cast<uint32_t*>(&hp1);
        }
        s0 += __shfl_xor_sync(0xffffffff, s0, 1);
        s0 += __shfl_xor_sync(0xffffffff, s0, 2);
        s1 += __shfl_xor_sync(0xffffffff, s1, 1);
        s1 += __shfl_xor_sync(0xffffffff, s1, 2);
        l0r = l0r * al0 + s0;
        l1r = l1r * al1 + s1;

        // ---- rescale O only when some lane's max moved ----
        bool no_rescale = (al0 == 1.f) && (al1 == 1.f);
        if (!__all_sync(0xffffffff, no_rescale)) {
            #pragma unroll
            for (int nt = 0; nt < 8; nt++) {
                o[nt][0] *= al0; o[nt][1] *= al0;
                o[nt][2] *= al1; o[nt][3] *= al1;
            }
        }

        // ---- O += P V : A-fragments come straight from p registers ----
        #pragma unroll
        for (int ks = 0; ks < 4; ks++) {
            const int kk = ks * 16 + 2 * tg;
            uint32_t a[4] = { p[2*ks][0], p[2*ks][1], p[2*ks+1][0], p[2*ks+1][1] };
            uint32_t b[8][2];
            #pragma unroll
            for (int nt = 0; nt < 8; nt++) {
                int d = nt * 8 + g;
                b[nt][0] = *(const uint32_t*)&Vc[d * FLD + kk];
                b[nt][1] = *(const uint32_t*)&Vc[d * FLD + kk + 8];
            }
            #pragma unroll
            for (int nt = 0; nt < 8; nt++)
                mma_f16(o[nt], a, b[nt]);
        }
    }

    // Epilogue: normalize, half-round, write ctx [B,S,D] half
    const int bb = bh >> 4;
    const int hh = bh & 15;
    const float il0 = 1.f / l0r, il1 = 1.f / l1r;
    #pragma unroll
    for (int nt = 0; nt < 8; nt++) {
        int d = nt * 8 + 2 * tg;
        *(uint32_t*)&ctx[((size_t)bb * SEQ + row0) * D_MODEL + hh * HDIM + d]
            = f2h2(o[nt][0] * il0, o[nt][1] * il0);
        *(uint32_t*)&ctx[((size_t)bb * SEQ + row1) * D_MODEL + hh * HDIM + d]
            = f2h2(o[nt][2] * il1, o[nt][3] * il1);
    }
}

// ---------------------------------------------------------------------------
extern "C" void kernel_launch(void* const* d_in, const int* in_sizes, int n_in,
                              void* d_out, int out_size)
{
    const float* in_q = (const float*)d_in[0];
    const float* in_k = (const float*)d_in[1];
    const float* in_v = (const float*)d_in[2];
    const float* Wq   = (const float*)d_in[3];
    const float* bq   = (const float*)d_in[4];
    const float* Wk   = (const float*)d_in[5];
    const float* bk   = (const float*)d_in[6];
    const float* Wv   = (const float*)d_in[7];
    const float* bv   = (const float*)d_in[8];
    const float* Wo   = (const float*)d_in[9];
    const float* bo   = (const float*)d_in[10];
    float* out = (float*)d_out;

    uint16_t *gq, *gk, *gv, *gc, *aq, *ak, *av, *wq, *wk, *wv, *wo;
    cudaGetSymbolAddress((void**)&gq, g_Q);
    cudaGetSymbolAddress((void**)&gk, g_K);
    cudaGetSymbolAddress((void**)&gv, g_V);
    cudaGetSymbolAddress((void**)&gc, g_C);
    cudaGetSymbolAddress((void**)&aq, g_Aq);
    cudaGetSymbolAddress((void**)&ak, g_Ak);
    cudaGetSymbolAddress((void**)&av, g_Av);
    cudaGetSymbolAddress((void**)&wq, g_Wq);
    cudaGetSymbolAddress((void**)&wk, g_Wk);
    cudaGetSymbolAddress((void**)&wv, g_Wv);
    cudaGetSymbolAddress((void**)&wo, g_Wo);

    static int attr_set = 0;
    if (!attr_set) {
        cudaFuncSetAttribute(gemm_h<1>, cudaFuncAttributeMaxDynamicSharedMemorySize, GEMM_SMEM);
        cudaFuncSetAttribute(gemm_h<0>, cudaFuncAttributeMaxDynamicSharedMemorySize, GEMM_SMEM);
        cudaFuncSetAttribute(flash_h,   cudaFuncAttributeMaxDynamicSharedMemorySize, FLASH_SMEM);
        attr_set = 1;
    }

    // Prepass: weights (transpose+round) and activations (round), 2 launches
    dim3 wt_grid(32, 32, 4);
    wtrans_kernel<<<wt_grid, dim3(32, 8)>>>(Wq, wq, Wk, wk, Wv, wv, Wo, wo);
    const int n8 = MROWS * D_MODEL / 8;   // 1M
    dim3 ac_grid((n8 + 255)/256, 1, 3);
    acvt_kernel<<<ac_grid, 256>>>((const float4*)in_q, (uint4*)aq,
                                  (const float4*)in_k, (uint4*)ak,
                                  (const float4*)in_v, (uint4*)av, n8);

    // Fused QKV projections, one launch (z selects problem)
    dim3 qkv_grid(D_MODEL / 128, MROWS / 128, 3);   // (8, 64, 3)
    gemm_h<1><<<qkv_grid, 256, GEMM_SMEM>>>(aq, wq, bq, gq,
                                            ak, wk, bk, gk,
                                            av, wv, bv, gv);

    dim3 attn_grid(SEQ / 128, BATCH * NHEADS);      // (16, 64)
    flash_h<<<attn_grid, 256, FLASH_SMEM>>>(gq, gk, gv, gc);

    // O-projection: A = half ctx, output fp32 + bias
    dim3 o_grid(D_MODEL / 128, MROWS / 128, 1);     // (8, 64)
    gemm_h<0><<<o_grid, 256, GEMM_SMEM>>>(gc, wo, bo, out,
                                          gc, wo, bo, out,
                                          gc, wo, bo, out);
}

// round 16
// speedup vs baseline: 1.2808x; 1.1243x over previous
#include <cuda_runtime.h>
#include <cuda_fp16.h>
#include <math.h>
#include <stdint.h>

#define D_MODEL 1024
#define NHEADS  16
#define HDIM    64
#define BATCH   4
#define SEQ     2048
#define MROWS   (BATCH*SEQ)   // 8192

// Scratch (device globals — no allocations allowed). Halves stored as uint16_t.
__device__ uint16_t g_Q[(size_t)MROWS * D_MODEL];   // [B,H,S,hd] half, PRE-SCALED by 0.125*log2e
__device__ uint16_t g_K[(size_t)MROWS * D_MODEL];   // [B,H,S,hd] half
__device__ uint16_t g_V[(size_t)MROWS * D_MODEL];   // [B,H,hd,S] half (pre-transposed!)
__device__ uint16_t g_C[(size_t)MROWS * D_MODEL];   // [B,S,D]    half
// half activations (pre-rounded)
__device__ uint16_t g_Aq[(size_t)MROWS * D_MODEL];
__device__ uint16_t g_Ak[(size_t)MROWS * D_MODEL];
__device__ uint16_t g_Av[(size_t)MROWS * D_MODEL];
// half TRANSPOSED weights: Wt[n][k] = half(W[k][n])
__device__ uint16_t g_Wq[(size_t)D_MODEL * D_MODEL];
__device__ uint16_t g_Wk[(size_t)D_MODEL * D_MODEL];
__device__ uint16_t g_Wv[(size_t)D_MODEL * D_MODEL];
__device__ uint16_t g_Wo[(size_t)D_MODEL * D_MODEL];

// 0.125 (1/sqrt(64)) * log2(e): Q is stored in the log2-softmax domain.
#define QSCALE (0.125f * 1.4426950408889634f)

__device__ __forceinline__ uint32_t f2h2(float a, float b) {
    __half2 h = __floats2half2_rn(a, b);
    return *reinterpret_cast<uint32_t*>(&h);
}

__device__ __forceinline__ uint32_t h2exp2(uint32_t x) {
    uint32_t r;
    asm("ex2.approx.f16x2 %0, %1;" : "=r"(r) : "r"(x));
    return r;
}

__device__ __forceinline__ void mma_f16(float c[4], const uint32_t a[4], const uint32_t b[2]) {
    asm volatile(
        "mma.sync.aligned.m16n8k16.row.col.f32.f16.f16.f32 "
        "{%0,%1,%2,%3},{%4,%5,%6,%7},{%8,%9},{%0,%1,%2,%3};"
        : "+f"(c[0]), "+f"(c[1]), "+f"(c[2]), "+f"(c[3])
        : "r"(a[0]), "r"(a[1]), "r"(a[2]), "r"(a[3]), "r"(b[0]), "r"(b[1]));
}

// ldmatrix x4: lane l supplies the 16B row address of (matrix l>>3, row l&7).
__device__ __forceinline__ void ldsm_x4(uint32_t* r, uint32_t addr) {
    asm volatile("ldmatrix.sync.aligned.m8n8.x4.shared.b16 {%0,%1,%2,%3}, [%4];"
        : "=r"(r[0]), "=r"(r[1]), "=r"(r[2]), "=r"(r[3]) : "r"(addr));
}

__device__ __forceinline__ uint32_t smem_u32(const void* p) {
    return (uint32_t)__cvta_generic_to_shared(p);
}

__device__ __forceinline__ void cp_async16(void* sptr, const void* gptr) {
    uint32_t s = (uint32_t)__cvta_generic_to_shared(sptr);
    asm volatile("cp.async.cg.shared.global [%0], [%1], 16;" :: "r"(s), "l"(gptr));
}
__device__ __forceinline__ void cp_commit() { asm volatile("cp.async.commit_group;"); }
template<int N> __device__ __forceinline__ void cp_wait() {
    asm volatile("cp.async.wait_group %0;" :: "n"(N));
}

// ---------------------------------------------------------------------------
// Activation prepass: fp32 -> half, 3 tensors (grid.z selects). 8 floats/thread.
// ---------------------------------------------------------------------------
__global__ void acvt_kernel(const float4* __restrict__ a0, uint4* __restrict__ o0,
                            const float4* __restrict__ a1, uint4* __restrict__ o1,
                            const float4* __restrict__ a2, uint4* __restrict__ o2,
                            int n8)
{
    const float4* in; uint4* out;
    switch (blockIdx.z) {
        case 0: in = a0; out = o0; break;
        case 1: in = a1; out = o1; break;
        default: in = a2; out = o2; break;
    }
    int i = blockIdx.x * blockDim.x + threadIdx.x;
    if (i < n8) {
        float4 u = in[2*i], v = in[2*i + 1];
        uint4 st;
        st.x = f2h2(u.x, u.y); st.y = f2h2(u.z, u.w);
        st.z = f2h2(v.x, v.y); st.w = f2h2(v.z, v.w);
        out[i] = st;
    }
}

// ---------------------------------------------------------------------------
// Weight prepass: transpose + half-round all 4 weight matrices.
// ---------------------------------------------------------------------------
__global__ void wtrans_kernel(const float* __restrict__ w0, uint16_t* __restrict__ o0,
                              const float* __restrict__ w1, uint16_t* __restrict__ o1,
                              const float* __restrict__ w2, uint16_t* __restrict__ o2,
                              const float* __restrict__ w3, uint16_t* __restrict__ o3)
{
    __shared__ float tile[32][33];
    const float* W; uint16_t* O;
    switch (blockIdx.z) {
        case 0: W = w0; O = o0; break;
        case 1: W = w1; O = o1; break;
        case 2: W = w2; O = o2; break;
        default: W = w3; O = o3; break;
    }
    int bx = blockIdx.x * 32;   // n block
    int by = blockIdx.y * 32;   // k block
    int tx = threadIdx.x, ty = threadIdx.y;
    #pragma unroll
    for (int i = 0; i < 4; i++)
        tile[ty + 8*i][tx] = W[(size_t)(by + ty + 8*i) * D_MODEL + bx + tx];
    __syncthreads();
    #pragma unroll
    for (int i = 0; i < 4; i++) {
        __half h = __float2half_rn(tile[tx][ty + 8*i]);
        O[(size_t)(bx + ty + 8*i) * D_MODEL + by + tx] = *reinterpret_cast<uint16_t*>(&h);
    }
}

// ===========================================================================
// fp16 tensor-core GEMM: C[M,N] = A[M,K] @ Wt^T + bias  (A, Wt both half)
// BM=BN=128, BK=32 halves, 256 threads (8 warps, 64x32 warp tiles),
// 4-stage cp.async pipeline with cp_wait<2>, ldmatrix fragment loads.
// REMAP=1: bias + half-round + head-split store; z==0 (Q) pre-scales by QSCALE;
//          z==2 (V) stores TRANSPOSED.
// ===========================================================================
#define ALD 40                    // halves per smem row (32 + 8 pad); 80 B
#define STG (128 * ALD)           // halves per operand per stage
#define NSTG 4
#define GEMM_SMEM (2 * NSTG * STG * 2)   // 81920 B

template<int REMAP>
__global__ __launch_bounds__(256, 2)
void gemm_h(const uint16_t* __restrict__ A0, const uint16_t* __restrict__ W0,
            const float* __restrict__ b0p, void* __restrict__ C0,
            const uint16_t* __restrict__ A1, const uint16_t* __restrict__ W1,
            const float* __restrict__ b1p, void* __restrict__ C1,
            const uint16_t* __restrict__ A2, const uint16_t* __restrict__ W2,
            const float* __restrict__ b2p, void* __restrict__ C2)
{
    const int K = D_MODEL, N = D_MODEL;
    extern __shared__ uint16_t smh[];
    uint16_t* As = smh;               // [NSTG][128][ALD]
    uint16_t* Bs = smh + NSTG * STG;  // [NSTG][128][ALD]

    const uint16_t *Ah, *Wt; const float* bias; void* Cv;
    const int zsel = blockIdx.z;
    switch (zsel) {
        case 0:  Ah = A0; Wt = W0; bias = b0p; Cv = C0; break;
        case 1:  Ah = A1; Wt = W1; bias = b1p; Cv = C1; break;
        default: Ah = A2; Wt = W2; bias = b2p; Cv = C2; break;
    }

    const int t    = threadIdx.x;
    const int lane = t & 31;
    const int warp = t >> 5;
    const int g    = lane >> 2;
    const int tg   = lane & 3;
    const int wm   = (warp & 1) * 64;
    const int wn   = (warp >> 1) * 32;
    const int m0   = blockIdx.y * 128;
    const int n0   = blockIdx.x * 128;

    // ldmatrix lane geometry (R10-verified)
    const int rowA = ((lane >> 3) & 1) * 8 + (lane & 7);
    const int kbA  = ((lane >> 4) & 1) * 16;   // byte bump for k+8
    const int rowB = ((lane >> 4) & 1) * 8 + (lane & 7);
    const int kbB  = ((lane >> 3) & 1) * 16;

    const uint32_t As_b = smem_u32(As);
    const uint32_t Bs_b = smem_u32(Bs);
    const uint32_t aLane = (uint32_t)(wm + rowA) * 80 + kbA;
    const uint32_t bLane = (uint32_t)(wn + rowB) * 80 + kbB;

    // cooperative load: 128 rows x 32 halves, 2 threads/row, 16 halves each
    const int lrow = t >> 1;
    const int lhlf = (t & 1) * 16;

    float acc[4][4][4] = {};

    const int NCHUNK = K / 32;   // 32

    // ---- Prologue: stages 0..2 ----
    #pragma unroll
    for (int st = 0; st < NSTG - 1; st++) {
        uint16_t* Ad = As + st * STG;
        uint16_t* Bd = Bs + st * STG;
        #pragma unroll
        for (int p = 0; p < 2; p++) {
            cp_async16(&Ad[lrow * ALD + lhlf + 8*p],
                       &Ah[(size_t)(m0 + lrow) * K + st * 32 + lhlf + 8*p]);
            cp_async16(&Bd[lrow * ALD + lhlf + 8*p],
                       &Wt[(size_t)(n0 + lrow) * K + st * 32 + lhlf + 8*p]);
        }
        cp_commit();
    }

    for (int c = 0; c < NCHUNK; c++) {
        if (c + 3 <= NCHUNK)      cp_wait<2>();
        else if (c + 2 == NCHUNK) cp_wait<1>();
        else                      cp_wait<0>();
        __syncthreads();
        const int s = c % NSTG;
        if (c + 3 < NCHUNK) {
            const int sn = (c + 3) % NSTG;
            const int kn = (c + 3) * 32;
            uint16_t* Ad = As + sn * STG;
            uint16_t* Bd = Bs + sn * STG;
            #pragma unroll
            for (int p = 0; p < 2; p++) {
                cp_async16(&Ad[lrow * ALD + lhlf + 8*p],
                           &Ah[(size_t)(m0 + lrow) * K + kn + lhlf + 8*p]);
                cp_async16(&Bd[lrow * ALD + lhlf + 8*p],
                           &Wt[(size_t)(n0 + lrow) * K + kn + lhlf + 8*p]);
            }
            cp_commit();
        }
        const uint32_t aBase = As_b + (uint32_t)s * (STG * 2) + aLane;
        const uint32_t bBase = Bs_b + (uint32_t)s * (STG * 2) + bLane;
        #pragma unroll
        for (int ks = 0; ks < 2; ks++) {
            uint32_t a[4][4], bp[2][4];
            #pragma unroll
            for (int mt = 0; mt < 4; mt++)
                ldsm_x4(a[mt], aBase + (uint32_t)mt * (16 * 80) + ks * 32);
            #pragma unroll
            for (int j = 0; j < 2; j++)
                ldsm_x4(bp[j], bBase + (uint32_t)j * (16 * 80) + ks * 32);
            #pragma unroll
            for (int mt = 0; mt < 4; mt++)
                #pragma unroll
                for (int nt = 0; nt < 4; nt++)
                    mma_f16(acc[mt][nt], a[mt], &bp[nt >> 1][(nt & 1) * 2]);
        }
    }

    // ---- Epilogue ----
    #pragma unroll
    for (int mt = 0; mt < 4; mt++) {
        #pragma unroll
        for (int nt = 0; nt < 4; nt++) {
            int n  = n0 + wn + nt * 8 + 2 * tg;
            float b0v = bias[n], b1v = bias[n + 1];
            #pragma unroll
            for (int half = 0; half < 2; half++) {
                int m = m0 + wm + mt * 16 + g + half * 8;
                float vx = acc[mt][nt][half*2 + 0] + b0v;
                float vy = acc[mt][nt][half*2 + 1] + b1v;
                if (REMAP) {
                    uint16_t* Ch = (uint16_t*)Cv;
                    int bb = m >> 11, srow = m & 2047;
                    int hh = n >> 6, dd = n & 63;
                    if (zsel == 0) {
                        // Q: fold attention scale * log2(e) (exp2 softmax domain)
                        vx *= QSCALE; vy *= QSCALE;
                    }
                    if (zsel == 2) {
                        // V: store transposed [B,H,hd,S]
                        __half h0 = __float2half_rn(vx), h1 = __float2half_rn(vy);
                        size_t base = ((size_t)(bb * NHEADS + hh)) * HDIM;
                        Ch[(base + dd)     * SEQ + srow] = *reinterpret_cast<uint16_t*>(&h0);
                        Ch[(base + dd + 1) * SEQ + srow] = *reinterpret_cast<uint16_t*>(&h1);
                    } else {
                        *(uint32_t*)&Ch[(((size_t)(bb * NHEADS + hh)) * SEQ + srow) * HDIM + dd]
                            = f2h2(vx, vy);
                    }
                } else {
                    float* Cf = (float*)Cv;
                    *(float2*)&Cf[(size_t)m * N + n] = make_float2(vx, vy);
                }
            }
        }
    }
}

// ---------------------------------------------------------------------------
// Causal flash attention, fp16 mma + ldmatrix, register-resident softmax & P.
// Q pre-scaled by 0.125*log2e; softmax via ex2.approx.f16x2.
// Q/K half [B,H,S,hd]; V half PRE-TRANSPOSED [B,H,hd,S]; ctx half [B,S,D].
// CTA = 256 threads (8 warps) on 128q x 64k tile; warp = 16q x 64k.
// Warps fully below the diagonal skip compute on the last k-tile.
// ---------------------------------------------------------------------------
#define FLD 72   // halves per smem row (64 + 8 pad); 144 B
#define FLASH_SMEM ((128*FLD + 2*64*FLD + 2*64*FLD) * 2)   // 55296 B

__global__ __launch_bounds__(256, 2)
void flash_h(const uint16_t* __restrict__ Q, const uint16_t* __restrict__ K,
             const uint16_t* __restrict__ V, uint16_t* __restrict__ ctx)
{
    extern __shared__ uint16_t smh[];
    uint16_t* Qs = smh;                    // [128][FLD]
    uint16_t* Ks = smh + 128 * FLD;        // [2][64][FLD]   Ks[k][d]
    uint16_t* Vs = Ks + 2 * 64 * FLD;      // [2][64][FLD]   Vs[d][k]

    const int t    = threadIdx.x;
    const int lane = t & 31;
    const int warp = t >> 5;
    const int g    = lane >> 2;
    const int tg   = lane & 3;
    const int wq   = warp * 16;
    const int qt   = (int)gridDim.x - 1 - (int)blockIdx.x;   // longest-first
    const int bh   = blockIdx.y;
    const int q0   = qt * 128;
    const int kt_max = 2 * qt + 1;

    // ldmatrix lane geometry (R10-verified)
    const int rowA = ((lane >> 3) & 1) * 8 + (lane & 7);
    const int kbA  = ((lane >> 4) & 1) * 16;
    const int rowB = ((lane >> 4) & 1) * 8 + (lane & 7);
    const int kbB  = ((lane >> 3) & 1) * 16;

    const uint32_t smb = smem_u32(smh);
    const uint32_t qa_base = smb + (uint32_t)(wq + rowA) * 144 + kbA;
    const uint32_t ks_off  = 128u * 144u;
    const uint32_t vs_off  = ks_off + 2u * 64u * 144u;
    const uint32_t bLane   = (uint32_t)rowB * 144 + kbB;

    // cooperative load indices
    const int qr = t >> 1, qc = (t & 1) * 32;        // Q: 128 rows, 2 thr/row
    const int kr = t >> 2, kc = (t & 3) * 16;        // K/V: 64 rows, 4 thr/row

    {
        const uint16_t* Qb = Q + ((size_t)bh * SEQ + q0) * HDIM;
        #pragma unroll
        for (int p = 0; p < 4; p++)
            cp_async16(&Qs[qr * FLD + qc + 8*p], &Qb[qr * HDIM + qc + 8*p]);
    }
    {
        const uint16_t* Kb = K + (size_t)bh * SEQ * HDIM;
        const uint16_t* Vb = V + (size_t)bh * HDIM * SEQ;
        #pragma unroll
        for (int p = 0; p < 2; p++) {
            cp_async16(&Ks[kr * FLD + kc + 8*p], &Kb[kr * HDIM + kc + 8*p]);
            cp_async16(&Vs[kr * FLD + kc + 8*p], &Vb[(size_t)kr * SEQ + kc + 8*p]);
        }
    }
    cp_commit();

    float m0r = -INFINITY, m1r = -INFINITY;
    float l0r = 0.f, l1r = 0.f;
    float o[8][4] = {};

    const int row0 = q0 + wq + g;
    const int row1 = row0 + 8;
    const int wq_last = q0 + wq + 15;   // last q row owned by this warp

    for (int kt = 0; kt <= kt_max; kt++) {
        cp_wait<0>();
        __syncthreads();
        const int s = kt & 1;
        if (kt < kt_max) {
            const int kn = (kt + 1) * 64;
            const uint16_t* Kb = K + ((size_t)bh * SEQ + kn) * HDIM;
            const uint16_t* Vb = V + (size_t)bh * HDIM * SEQ + kn;
            uint16_t* Kn = Ks + (s ^ 1) * 64 * FLD;
            uint16_t* Vn = Vs + (s ^ 1) * 64 * FLD;
            #pragma unroll
            for (int p = 0; p < 2; p++) {
                cp_async16(&Kn[kr * FLD + kc + 8*p], &Kb[kr * HDIM + kc + 8*p]);
                cp_async16(&Vn[kr * FLD + kc + 8*p], &Vb[(size_t)kr * SEQ + kc + 8*p]);
            }
            cp_commit();
        }
        const int k0 = kt * 64;
        if (k0 > wq_last) continue;   // warp fully masked on this tile (uniform)

        const uint32_t Kc_b = smb + ks_off + (uint32_t)s * (64 * 144) + bLane;
        const uint32_t Vc_b = smb + vs_off + (uint32_t)s * (64 * 144) + bLane;

        // ---- S = (Q*QSCALE) K^T  (log2-domain scores) ----
        float sc[8][4] = {};
        #pragma unroll
        for (int ks = 0; ks < 4; ks++) {
            uint32_t a[4], bp[4][4];
            ldsm_x4(a, qa_base + ks * 32);
            #pragma unroll
            for (int j = 0; j < 4; j++)
                ldsm_x4(bp[j], Kc_b + (uint32_t)j * (16 * 144) + ks * 32);
            #pragma unroll
            for (int nt = 0; nt < 8; nt++)
                mma_f16(sc[nt], a, &bp[nt >> 1][(nt & 1) * 2]);
        }

        // ---- causal mask (select only) ----
        if (k0 + 63 > row0) {
            #pragma unroll
            for (int nt = 0; nt < 8; nt++) {
                int c = k0 + nt * 8 + 2 * tg;
                if (c     > row0) sc[nt][0] = -INFINITY;
                if (c + 1 > row0) sc[nt][1] = -INFINITY;
                if (c     > row1) sc[nt][2] = -INFINITY;
                if (c + 1 > row1) sc[nt][3] = -INFINITY;
            }
        }

        // ---- row max (registers + quad shuffle) ----
        float mx0 = -INFINITY, mx1 = -INFINITY;
        #pragma unroll
        for (int nt = 0; nt < 8; nt++) {
            mx0 = fmaxf(mx0, fmaxf(sc[nt][0], sc[nt][1]));
            mx1 = fmaxf(mx1, fmaxf(sc[nt][2], sc[nt][3]));
        }
        mx0 = fmaxf(mx0, __shfl_xor_sync(0xffffffff, mx0, 1));
        mx0 = fmaxf(mx0, __shfl_xor_sync(0xffffffff, mx0, 2));
        mx1 = fmaxf(mx1, __shfl_xor_sync(0xffffffff, mx1, 1));
        mx1 = fmaxf(mx1, __shfl_xor_sync(0xffffffff, mx1, 2));

        float mn0 = fmaxf(m0r, mx0), mn1 = fmaxf(m1r, mx1);
        float al0 = exp2f(m0r - mn0), al1 = exp2f(m1r - mn1);
        m0r = mn0; m1r = mn1;

        // ---- exp2 via f16x2 MUFU, row sums, P stays in REGISTERS ----
        uint32_t p[8][2];
        float s0 = 0.f, s1 = 0.f;
        #pragma unroll
        for (int nt = 0; nt < 8; nt++) {
            uint32_t hp0 = h2exp2(f2h2(sc[nt][0] - mn0, sc[nt][1] - mn0));
            uint32_t hp1 = h2exp2(f2h2(sc[nt][2] - mn1, sc[nt][3] - mn1));
            float2 r0 = __half22float2(*reinterpret_cast<__half2*>(&hp0));
            float2 r1 = __half22float2(*reinterpret_cast<__half2*>(&hp1));
            s0 += r0.x + r0.y;
            s1 += r1.x + r1.y;
            p[nt][0] = hp0;
            p[nt][1] = hp1;
        }
        s0 += __shfl_xor_sync(0xffffffff, s0, 1);
        s0 += __shfl_xor_sync(0xffffffff, s0, 2);
        s1 += __shfl_xor_sync(0xffffffff, s1, 1);
        s1 += __shfl_xor_sync(0xffffffff, s1, 2);
        l0r = l0r * al0 + s0;
        l1r = l1r * al1 + s1;

        // ---- rescale O only when some lane's max moved ----
        bool no_rescale = (al0 == 1.f) && (al1 == 1.f);
        if (!__all_sync(0xffffffff, no_rescale)) {
            #pragma unroll
            for (int nt = 0; nt < 8; nt++) {
                o[nt][0] *= al0; o[nt][1] *= al0;
                o[nt][2] *= al1; o[nt][3] *= al1;
            }
        }

        // ---- O += P V : A-fragments come straight from p registers ----
        #pragma unroll
        for (int ks = 0; ks < 4; ks++) {
            uint32_t a[4] = { p[2*ks][0], p[2*ks][1], p[2*ks+1][0], p[2*ks+1][1] };
            uint32_t bp[4][4];
            #pragma unroll
            for (int j = 0; j < 4; j++)
                ldsm_x4(bp[j], Vc_b + (uint32_t)j * (16 * 144) + ks * 32);
            #pragma unroll
            for (int nt = 0; nt < 8; nt++)
                mma_f16(o[nt], a, &bp[nt >> 1][(nt & 1) * 2]);
        }
    }

    // Epilogue: normalize, half-round, write ctx [B,S,D] half
    const int bb = bh >> 4;
    const int hh = bh & 15;
    const float il0 = 1.f / l0r, il1 = 1.f / l1r;
    #pragma unroll
    for (int nt = 0; nt < 8; nt++) {
        int d = nt * 8 + 2 * tg;
        *(uint32_t*)&ctx[((size_t)bb * SEQ + row0) * D_MODEL + hh * HDIM + d]
            = f2h2(o[nt][0] * il0, o[nt][1] * il0);
        *(uint32_t*)&ctx[((size_t)bb * SEQ + row1) * D_MODEL + hh * HDIM + d]
            = f2h2(o[nt][2] * il1, o[nt][3] * il1);
    }
}

// ---------------------------------------------------------------------------
extern "C" void kernel_launch(void* const* d_in, const int* in_sizes, int n_in,
                              void* d_out, int out_size)
{
    const float* in_q = (const float*)d_in[0];
    const float* in_k = (const float*)d_in[1];
    const float* in_v = (const float*)d_in[2];
    const float* Wq   = (const float*)d_in[3];
    const float* bq   = (const float*)d_in[4];
    const float* Wk   = (const float*)d_in[5];
    const float* bk   = (const float*)d_in[6];
    const float* Wv   = (const float*)d_in[7];
    const float* bv   = (const float*)d_in[8];
    const float* Wo   = (const float*)d_in[9];
    const float* bo   = (const float*)d_in[10];
    float* out = (float*)d_out;

    uint16_t *gq, *gk, *gv, *gc, *aq, *ak, *av, *wq, *wk, *wv, *wo;
    cudaGetSymbolAddress((void**)&gq, g_Q);
    cudaGetSymbolAddress((void**)&gk, g_K);
    cudaGetSymbolAddress((void**)&gv, g_V);
    cudaGetSymbolAddress((void**)&gc, g_C);
    cudaGetSymbolAddress((void**)&aq, g_Aq);
    cudaGetSymbolAddress((void**)&ak, g_Ak);
    cudaGetSymbolAddress((void**)&av, g_Av);
    cudaGetSymbolAddress((void**)&wq, g_Wq);
    cudaGetSymbolAddress((void**)&wk, g_Wk);
    cudaGetSymbolAddress((void**)&wv, g_Wv);
    cudaGetSymbolAddress((void**)&wo, g_Wo);

    static int attr_set = 0;
    if (!attr_set) {
        cudaFuncSetAttribute(gemm_h<1>, cudaFuncAttributeMaxDynamicSharedMemorySize, GEMM_SMEM);
        cudaFuncSetAttribute(gemm_h<0>, cudaFuncAttributeMaxDynamicSharedMemorySize, GEMM_SMEM);
        cudaFuncSetAttribute(flash_h,   cudaFuncAttributeMaxDynamicSharedMemorySize, FLASH_SMEM);
        attr_set = 1;
    }

    // Prepass: weights (transpose+round) and activations (round), 2 launches
    dim3 wt_grid(32, 32, 4);
    wtrans_kernel<<<wt_grid, dim3(32, 8)>>>(Wq, wq, Wk, wk, Wv, wv, Wo, wo);
    const int n8 = MROWS * D_MODEL / 8;   // 1M
    dim3 ac_grid((n8 + 255)/256, 1, 3);
    acvt_kernel<<<ac_grid, 256>>>((const float4*)in_q, (uint4*)aq,
                                  (const float4*)in_k, (uint4*)ak,
                                  (const float4*)in_v, (uint4*)av, n8);

    // Fused QKV projections, one launch (z selects problem)
    dim3 qkv_grid(D_MODEL / 128, MROWS / 128, 3);   // (8, 64, 3)
    gemm_h<1><<<qkv_grid, 256, GEMM_SMEM>>>(aq, wq, bq, gq,
                                            ak, wk, bk, gk,
                                            av, wv, bv, gv);

    dim3 attn_grid(SEQ / 128, BATCH * NHEADS);      // (16, 64)
    flash_h<<<attn_grid, 256, FLASH_SMEM>>>(gq, gk, gv, gc);

    // O-projection: A = half ctx, output fp32 + bias
    dim3 o_grid(D_MODEL / 128, MROWS / 128, 1);     // (8, 64)
    gemm_h<0><<<o_grid, 256, GEMM_SMEM>>>(gc, wo, bo, out,
                                          gc, wo, bo, out,
                                          gc, wo, bo, out);
}